// round 1
// baseline (speedup 1.0000x reference)
#include <cuda_runtime.h>
#include <math.h>

#define BATCH 16
#define CH    64
#define NPIX  25600          // 160*160
#define HID   256
#define KSEL  20480          // ceil(25600*0.8)
#define TOK   64
#define TP    68             // padded token stride (multiple of 4 for float4)

// ---------------- static scratch (no allocation allowed) ----------------
__device__ unsigned      g_thresh[BATCH];
__device__ int           g_ties[BATCH];
__device__ unsigned char g_flags[BATCH * NPIX];

// order-preserving float -> unsigned key (larger float <-> larger key)
__device__ __forceinline__ unsigned fkey(float f) {
    unsigned u = __float_as_uint(f);
    return (u & 0x80000000u) ? ~u : (u | 0x80000000u);
}

__device__ __forceinline__ float gelu_f(float v) {
    // JAX default gelu (approximate=True): 0.5*x*(1+tanh(sqrt(2/pi)*(x+0.044715 x^3)))
    const float k0 = 0.7978845608028654f;
    const float k1 = 0.044715f;
    float inner = k0 * (v + k1 * v * v * v);
    return 0.5f * v * (1.0f + tanhf(inner));
}

// ---------------- kernel 1: per-batch radix select (K-th largest) ----------------
__global__ void select_kernel(const float* __restrict__ prop) {
    int b = blockIdx.x;
    const float* p = prop + (size_t)b * NPIX;
    __shared__ unsigned hist[256];
    __shared__ unsigned s_prefix;
    __shared__ int s_k;
    if (threadIdx.x == 0) { s_prefix = 0u; s_k = KSEL; }
    __syncthreads();

    for (int pass = 3; pass >= 0; --pass) {
        int shift = pass * 8;
        hist[threadIdx.x] = 0u;
        __syncthreads();
        unsigned prefix = s_prefix;
        unsigned highmask = (pass == 3) ? 0u : (0xFFFFFFFFu << (shift + 8));
        for (int i = threadIdx.x; i < NPIX; i += 256) {
            unsigned u = fkey(p[i]);
            if ((u & highmask) == prefix)
                atomicAdd(&hist[(u >> shift) & 255u], 1u);
        }
        __syncthreads();
        if (threadIdx.x == 0) {
            int k = s_k;
            unsigned cum = 0;
            for (int d = 255; d >= 0; --d) {
                unsigned cnt = hist[d];
                if ((unsigned)k <= cum + cnt) {
                    s_prefix = prefix | ((unsigned)d << shift);
                    s_k = k - (int)cum;
                    break;
                }
                cum += cnt;
            }
        }
        __syncthreads();
    }
    if (threadIdx.x == 0) {
        g_thresh[b] = s_prefix;   // exact key of K-th largest
        g_ties[b]   = s_k;        // how many ==threshold elements to include (lowest index first)
    }
}

// ---------------- kernel 2: selected-token flags (index-ordered tie break) ----------------
__global__ void flags_kernel(const float* __restrict__ prop) {
    int b = blockIdx.x;
    const float* p = prop + (size_t)b * NPIX;
    unsigned T = g_thresh[b];
    int ties = g_ties[b];
    __shared__ int s_carry;
    __shared__ int warp_sums[8];
    int tid = threadIdx.x;
    int lane = tid & 31, w = tid >> 5;
    if (tid == 0) s_carry = 0;
    __syncthreads();

    for (int base = 0; base < NPIX; base += 256) {
        int i = base + tid;
        unsigned u = fkey(p[i]);
        int gt = (u > T);
        int eq = (u == T);
        unsigned ball = __ballot_sync(0xffffffffu, eq);
        int pre = __popc(ball & ((1u << lane) - 1u));
        if (lane == 0) warp_sums[w] = __popc(ball);
        __syncthreads();
        int woff = 0;
        for (int x = 0; x < w; ++x) woff += warp_sums[x];
        int rank = s_carry + woff + pre;
        int sel = gt || (eq && rank < ties);
        g_flags[(size_t)b * NPIX + i] = (unsigned char)sel;
        __syncthreads();
        if (tid == 0) {
            int tot = 0;
            for (int x = 0; x < 8; ++x) tot += warp_sums[x];
            s_carry += tot;
        }
        __syncthreads();
    }
}

// ---------------- kernel 3: fused LN + MLP(2 layers) + residual, per 64-token tile ----------
// smem layout (floats):
//  sT   [64][68]     @ 0        (current token vectors, [c][t])
//  sXn  [64][68]     @ 4352     (normalized, [c][t])
//  sH   [128][68]    @ 8704     (gelu'd hidden j-chunk, [j][t])
//  sW1  [64][256]    @ 17408    ([c][j])
//  sW2  [256][64]    @ 33792    ([j][c])
//  sB1  [256]        @ 50176
//  sB2  [64]         @ 50432
//  sLS  [64]         @ 50496
//  sLB  [64]         @ 50560
//  sMu  [64]         @ 50624
//  sRs  [64]         @ 50688
//  sFlag[64] (int)   @ 50752
#define SMEM_FLOATS 50816
#define SMEM_BYTES  (SMEM_FLOATS * 4)

__global__ void __launch_bounds__(256, 1)
main_kernel(const float* __restrict__ x,
            const float* __restrict__ lnscale, const float* __restrict__ lnbias,
            const float* __restrict__ w1, const float* __restrict__ b1,
            const float* __restrict__ w2, const float* __restrict__ b2,
            float* __restrict__ out) {
    extern __shared__ float sm[];
    float* sT  = sm;
    float* sXn = sm + 4352;
    float* sH  = sm + 8704;
    float* sW1 = sm + 17408;
    float* sW2 = sm + 33792;
    float* sB1 = sm + 50176;
    float* sB2 = sm + 50432;
    float* sLS = sm + 50496;
    float* sLB = sm + 50560;
    float* sMu = sm + 50624;
    float* sRs = sm + 50688;
    int*   sFlag = (int*)(sm + 50752);

    int b  = blockIdx.y;
    int n0 = blockIdx.x * TOK;
    int tid = threadIdx.x;

    const float* xb = x + (size_t)b * CH * NPIX + n0;

    // ---- load 64-token tile: sT[c][t] = x[b][c][n0+t] ----
    {
        int t = tid & 63, cq = tid >> 6;
        #pragma unroll
        for (int k = 0; k < 16; ++k) {
            int c = k * 4 + cq;
            sT[c * TP + t] = xb[(size_t)c * NPIX + t];
        }
        if (tid < TOK) sFlag[tid] = g_flags[(size_t)b * NPIX + n0 + tid];
    }
    __syncthreads();

    int tg = tid >> 4;          // token group (0..15) -> t0 = tg*4
    int cg = tid & 15;          // col group (0..15)
    int t0 = tg * 4;

    for (int layer = 0; layer < 2; ++layer) {
        // ---- stage weights for this layer ----
        {
            const float4* gw1 = (const float4*)(w1 + (size_t)layer * CH * HID);
            const float4* gw2 = (const float4*)(w2 + (size_t)layer * HID * CH);
            float4* s1 = (float4*)sW1;
            float4* s2 = (float4*)sW2;
            for (int i = tid; i < CH * HID / 4; i += 256) { s1[i] = gw1[i]; s2[i] = gw2[i]; }
            if (tid < HID) sB1[tid] = b1[layer * HID + tid];
            if (tid < CH)  { sB2[tid] = b2[layer * CH + tid];
                             sLS[tid] = lnscale[layer * CH + tid];
                             sLB[tid] = lnbias[layer * CH + tid]; }
        }
        // ---- LN stats: 4 threads per token ----
        {
            int tok = tid >> 2, part = tid & 3;
            float s = 0.f, s2 = 0.f;
            #pragma unroll
            for (int k = 0; k < 16; ++k) {
                float v = sT[(part * 16 + k) * TP + tok];
                s += v; s2 += v * v;
            }
            s  += __shfl_xor_sync(0xffffffffu, s, 1);
            s2 += __shfl_xor_sync(0xffffffffu, s2, 1);
            s  += __shfl_xor_sync(0xffffffffu, s, 2);
            s2 += __shfl_xor_sync(0xffffffffu, s2, 2);
            if (part == 0) {
                float mu  = s * (1.0f / 64.0f);
                float var = s2 * (1.0f / 64.0f) - mu * mu;
                sMu[tok] = mu;
                sRs[tok] = rsqrtf(var + 1e-5f);
            }
        }
        __syncthreads();
        // ---- normalized tile ----
        {
            int t = tid & 63, cq = tid >> 6;
            float mu = sMu[t], rs = sRs[t];
            #pragma unroll
            for (int k = 0; k < 16; ++k) {
                int c = k * 4 + cq;
                sXn[c * TP + t] = (sT[c * TP + t] - mu) * rs * sLS[c] + sLB[c];
            }
        }
        __syncthreads();

        float oacc[16];
        #pragma unroll
        for (int i = 0; i < 16; ++i) oacc[i] = 0.f;
        int c0 = cg * 4;

        for (int jc = 0; jc < 2; ++jc) {
            // ---- GEMM1: H[128j-chunk][64t] = gelu(Xn @ W1 + b1); thread does 4t x 8j ----
            float ha[32];
            #pragma unroll
            for (int i = 0; i < 32; ++i) ha[i] = 0.f;
            int j0 = jc * 128 + cg * 8;
            #pragma unroll 4
            for (int c = 0; c < CH; ++c) {
                float4 a  = *(const float4*)(sXn + c * TP + t0);
                float4 w0 = *(const float4*)(sW1 + c * HID + j0);
                float4 w1v= *(const float4*)(sW1 + c * HID + j0 + 4);
                float av[4] = {a.x, a.y, a.z, a.w};
                float wv[8] = {w0.x, w0.y, w0.z, w0.w, w1v.x, w1v.y, w1v.z, w1v.w};
                #pragma unroll
                for (int tt = 0; tt < 4; ++tt)
                    #pragma unroll
                    for (int jj = 0; jj < 8; ++jj)
                        ha[tt * 8 + jj] += av[tt] * wv[jj];
            }
            #pragma unroll
            for (int jj = 0; jj < 8; ++jj) {
                int jr = cg * 8 + jj;
                float bb = sB1[jc * 128 + jr];
                float4 hv;
                hv.x = gelu_f(ha[0 * 8 + jj] + bb);
                hv.y = gelu_f(ha[1 * 8 + jj] + bb);
                hv.z = gelu_f(ha[2 * 8 + jj] + bb);
                hv.w = gelu_f(ha[3 * 8 + jj] + bb);
                *(float4*)(sH + jr * TP + t0) = hv;
            }
            __syncthreads();
            // ---- GEMM2 accumulate: out[64t][64c] += H @ W2; thread does 4t x 4c ----
            #pragma unroll 4
            for (int j = 0; j < 128; ++j) {
                float4 a = *(const float4*)(sH + j * TP + t0);
                float4 w = *(const float4*)(sW2 + (jc * 128 + j) * CH + c0);
                float av[4] = {a.x, a.y, a.z, a.w};
                float wv[4] = {w.x, w.y, w.z, w.w};
                #pragma unroll
                for (int tt = 0; tt < 4; ++tt)
                    #pragma unroll
                    for (int cc = 0; cc < 4; ++cc)
                        oacc[tt * 4 + cc] += av[tt] * wv[cc];
            }
            __syncthreads();
        }
        // ---- gated residual add (unselected tokens keep t = x) ----
        #pragma unroll
        for (int tt = 0; tt < 4; ++tt) {
            if (sFlag[t0 + tt]) {
                #pragma unroll
                for (int cc = 0; cc < 4; ++cc)
                    sT[(c0 + cc) * TP + (t0 + tt)] += oacc[tt * 4 + cc] + sB2[c0 + cc];
            }
        }
        __syncthreads();
    }

    // ---- store tile ----
    {
        int t = tid & 63, cq = tid >> 6;
        float* ob = out + (size_t)b * CH * NPIX + n0;
        #pragma unroll
        for (int k = 0; k < 16; ++k) {
            int c = k * 4 + cq;
            ob[(size_t)c * NPIX + t] = sT[c * TP + t];
        }
    }
}

// ---------------- launch ----------------
extern "C" void kernel_launch(void* const* d_in, const int* in_sizes, int n_in,
                              void* d_out, int out_size) {
    const float* x    = (const float*)d_in[0];
    const float* prop = (const float*)d_in[1];
    const float* lns  = (const float*)d_in[2];
    const float* lnb  = (const float*)d_in[3];
    const float* w1   = (const float*)d_in[4];
    const float* b1   = (const float*)d_in[5];
    const float* w2   = (const float*)d_in[6];
    const float* b2   = (const float*)d_in[7];
    float* out = (float*)d_out;

    cudaFuncSetAttribute(main_kernel, cudaFuncAttributeMaxDynamicSharedMemorySize, SMEM_BYTES);

    select_kernel<<<BATCH, 256>>>(prop);
    flags_kernel<<<BATCH, 256>>>(prop);
    dim3 grid(NPIX / TOK, BATCH);
    main_kernel<<<grid, 256, SMEM_BYTES>>>(x, lns, lnb, w1, b1, w2, b2, out);
}

// round 2
// speedup vs baseline: 2.6523x; 2.6523x over previous
#include <cuda_runtime.h>
#include <cuda_bf16.h>
#include <math.h>

#define BATCH 16
#define CH    64
#define NPIX  25600          // 160*160
#define HID   256
#define KSEL  20480          // ceil(25600*0.8)
#define TOKB  128            // tokens per block
#define NTHR  256            // 8 warps

// element strides
#define ST_S  68             // sT fp32 row stride
#define XN_S  72             // bf16 (144B rows -> ldmatrix conflict-free)
#define W1_S  136            // bf16 (272B rows)
#define W2_S  72
#define H_S   136

// smem byte offsets
#define OFF_T    0            // 128*68*4  = 34816
#define OFF_XNH  34816        // 128*72*2  = 18432
#define OFF_XNL  53248
#define OFF_W1H  71680        // 64*136*2  = 17408
#define OFF_W1L  89088
#define OFF_W2H  106496       // 128*72*2  = 18432
#define OFF_W2L  124928
#define OFF_HH   143360       // 128*136*2 = 34816
#define OFF_HL   178176
#define OFF_B1   212992       // 256*4
#define OFF_B2   214016       // 64*4
#define OFF_LS   214272
#define OFF_LB   214528
#define OFF_FLAG 214784       // 128*4
#define SMEM_BYTES 215296

// ---------------- static scratch ----------------
__device__ unsigned      g_thresh[BATCH];
__device__ int           g_ties[BATCH];
__device__ unsigned char g_flags[BATCH * NPIX];

__device__ __forceinline__ unsigned fkey(float f) {
    unsigned u = __float_as_uint(f);
    return (u & 0x80000000u) ? ~u : (u | 0x80000000u);
}

__device__ __forceinline__ float gelu_f(float v) {
    float inner = 0.7978845608028654f * (v + 0.044715f * v * v * v);
    float t;
    asm("tanh.approx.f32 %0, %1;" : "=f"(t) : "f"(inner));
    return 0.5f * v * (1.0f + t);
}

// split fp32 pair into hi/lo bf16 pairs (packed as u32)
__device__ __forceinline__ void split2(float2 v, unsigned &hi, unsigned &lo) {
    __nv_bfloat162 h = __float22bfloat162_rn(v);
    float2 r;
    r.x = v.x - __bfloat162float(h.x);
    r.y = v.y - __bfloat162float(h.y);
    __nv_bfloat162 l = __float22bfloat162_rn(r);
    hi = *(unsigned*)&h;
    lo = *(unsigned*)&l;
}

__device__ __forceinline__ void ldsm_x4(unsigned r[4], unsigned addr) {
    asm volatile("ldmatrix.sync.aligned.m8n8.x4.shared.b16 {%0,%1,%2,%3}, [%4];"
                 : "=r"(r[0]), "=r"(r[1]), "=r"(r[2]), "=r"(r[3]) : "r"(addr));
}
__device__ __forceinline__ void ldsm_x4t(unsigned r[4], unsigned addr) {
    asm volatile("ldmatrix.sync.aligned.m8n8.x4.trans.shared.b16 {%0,%1,%2,%3}, [%4];"
                 : "=r"(r[0]), "=r"(r[1]), "=r"(r[2]), "=r"(r[3]) : "r"(addr));
}
__device__ __forceinline__ void mma_bf16(float* d, const unsigned a[4], unsigned b0, unsigned b1) {
    asm volatile("mma.sync.aligned.m16n8k16.row.col.f32.bf16.bf16.f32 "
                 "{%0,%1,%2,%3}, {%4,%5,%6,%7}, {%8,%9}, {%0,%1,%2,%3};"
                 : "+f"(d[0]), "+f"(d[1]), "+f"(d[2]), "+f"(d[3])
                 : "r"(a[0]), "r"(a[1]), "r"(a[2]), "r"(a[3]), "r"(b0), "r"(b1));
}

// ---------------- kernel 1: per-batch radix select (K-th largest) ----------------
__global__ void select_kernel(const float* __restrict__ prop) {
    int b = blockIdx.x;
    const float* p = prop + (size_t)b * NPIX;
    __shared__ unsigned hist[256];
    __shared__ unsigned s_prefix;
    __shared__ int s_k;
    if (threadIdx.x == 0) { s_prefix = 0u; s_k = KSEL; }
    __syncthreads();

    for (int pass = 3; pass >= 0; --pass) {
        int shift = pass * 8;
        if (threadIdx.x < 256) hist[threadIdx.x] = 0u;
        __syncthreads();
        unsigned prefix = s_prefix;
        unsigned highmask = (pass == 3) ? 0u : (0xFFFFFFFFu << (shift + 8));
        for (int i = threadIdx.x; i < NPIX; i += 1024) {
            unsigned u = fkey(p[i]);
            if ((u & highmask) == prefix)
                atomicAdd(&hist[(u >> shift) & 255u], 1u);
        }
        __syncthreads();
        if (threadIdx.x == 0) {
            int k = s_k;
            unsigned cum = 0;
            for (int d = 255; d >= 0; --d) {
                unsigned cnt = hist[d];
                if ((unsigned)k <= cum + cnt) {
                    s_prefix = prefix | ((unsigned)d << shift);
                    s_k = k - (int)cum;
                    break;
                }
                cum += cnt;
            }
        }
        __syncthreads();
    }
    if (threadIdx.x == 0) {
        g_thresh[b] = s_prefix;
        g_ties[b]   = s_k;
    }
}

// ---------------- kernel 2: selected-token flags ----------------
__global__ void flags_kernel(const float* __restrict__ prop) {
    int b = blockIdx.x;
    const float* p = prop + (size_t)b * NPIX;
    unsigned T = g_thresh[b];
    int ties = g_ties[b];
    __shared__ int s_carry;
    __shared__ int warp_sums[32];
    int tid = threadIdx.x;
    int lane = tid & 31, w = tid >> 5;
    if (tid == 0) s_carry = 0;
    __syncthreads();

    for (int base = 0; base < NPIX; base += 1024) {
        int i = base + tid;
        unsigned u = fkey(p[i]);
        int gt = (u > T);
        int eq = (u == T);
        unsigned ball = __ballot_sync(0xffffffffu, eq);
        int pre = __popc(ball & ((1u << lane) - 1u));
        if (lane == 0) warp_sums[w] = __popc(ball);
        __syncthreads();
        int woff = 0;
        for (int xw = 0; xw < w; ++xw) woff += warp_sums[xw];
        int rank = s_carry + woff + pre;
        int sel = gt || (eq && rank < ties);
        g_flags[(size_t)b * NPIX + i] = (unsigned char)sel;
        __syncthreads();
        if (tid == 0) {
            int tot = 0;
            for (int xw = 0; xw < 32; ++xw) tot += warp_sums[xw];
            s_carry += tot;
        }
        __syncthreads();
    }
}

// ---------------- kernel 3: fused LN + MLP via bf16 3-pass tensor cores ----------
__global__ void __launch_bounds__(NTHR, 1)
main_kernel(const float* __restrict__ x,
            const float* __restrict__ lnscale, const float* __restrict__ lnbias,
            const float* __restrict__ w1g, const float* __restrict__ b1g,
            const float* __restrict__ w2g, const float* __restrict__ b2g,
            float* __restrict__ out) {
    extern __shared__ char sm[];
    float* sT  = (float*)(sm + OFF_T);
    float* sB1 = (float*)(sm + OFF_B1);
    float* sB2 = (float*)(sm + OFF_B2);
    float* sLS = (float*)(sm + OFF_LS);
    float* sLB = (float*)(sm + OFF_LB);
    int*   sFlag = (int*)(sm + OFF_FLAG);
    unsigned* xh = (unsigned*)(sm + OFF_XNH);
    unsigned* xl = (unsigned*)(sm + OFF_XNL);
    unsigned* w1h = (unsigned*)(sm + OFF_W1H);
    unsigned* w1l = (unsigned*)(sm + OFF_W1L);
    unsigned* w2h = (unsigned*)(sm + OFF_W2H);
    unsigned* w2l = (unsigned*)(sm + OFF_W2L);
    unsigned* hh = (unsigned*)(sm + OFF_HH);
    unsigned* hl = (unsigned*)(sm + OFF_HL);
    unsigned smem_base = (unsigned)__cvta_generic_to_shared(sm);

    int tid = threadIdx.x;
    int lane = tid & 31, w = tid >> 5;
    int tb = w * 16;                 // this warp's token rows [tb, tb+16)
    int b = blockIdx.y, n0 = blockIdx.x * TOKB;

    // ---- load x tile: sT[t][c] ----
    const float* xb = x + (size_t)b * CH * NPIX + n0;
    for (int i = tid; i < TOKB * CH; i += NTHR) {
        int t = i & (TOKB - 1);
        int c = i >> 7;
        sT[t * ST_S + c] = xb[(size_t)c * NPIX + t];
    }
    if (tid < TOKB) sFlag[tid] = g_flags[(size_t)b * NPIX + n0 + tid];
    __syncthreads();

    float d2[32];
    int r15 = lane & 15;
    int colsel = ((lane >> 4) & 1) * 8;

    for (int layer = 0; layer < 2; ++layer) {
        if (tid < HID) sB1[tid] = b1g[layer * HID + tid];
        if (tid < CH) {
            sB2[tid] = b2g[layer * CH + tid];
            sLS[tid] = lnscale[layer * CH + tid];
            sLB[tid] = lnbias[layer * CH + tid];
        }
        __syncthreads();

        // ---- LN (warp-local): 2 lanes per token ----
        {
            int r = lane >> 1, half = lane & 1;
            int t = tb + r;
            const float* row = sT + t * ST_S + half * 32;
            float s = 0.f, s2 = 0.f;
            #pragma unroll
            for (int k = 0; k < 32; k += 4) {
                float4 v = *(const float4*)(row + k);
                s  += v.x + v.y + v.z + v.w;
                s2 += v.x * v.x + v.y * v.y + v.z * v.z + v.w * v.w;
            }
            s  += __shfl_xor_sync(0xffffffffu, s, 1);
            s2 += __shfl_xor_sync(0xffffffffu, s2, 1);
            float mu = s * (1.f / 64.f);
            float var = s2 * (1.f / 64.f) - mu * mu;
            float rs = rsqrtf(var + 1e-5f);
            #pragma unroll
            for (int k = 0; k < 32; k += 2) {
                int c = half * 32 + k;
                float2 v = *(const float2*)(sT + t * ST_S + c);
                v.x = (v.x - mu) * rs * sLS[c]   + sLB[c];
                v.y = (v.y - mu) * rs * sLS[c+1] + sLB[c+1];
                unsigned hi, lo; split2(v, hi, lo);
                xh[(t * XN_S + c) >> 1] = hi;
                xl[(t * XN_S + c) >> 1] = lo;
            }
        }
        __syncwarp();

        #pragma unroll
        for (int i = 0; i < 32; ++i) d2[i] = 0.f;

        for (int jc = 0; jc < 2; ++jc) {
            __syncthreads();
            // ---- stage W1 chunk [64 c][128 j] and W2 chunk [128 j][64 c] hi/lo ----
            for (int i = tid; i < 64 * 128 / 2; i += NTHR) {
                int flat = i * 2;
                int c = flat >> 7, j = flat & 127;
                float2 v = *(const float2*)(w1g + (size_t)(layer * CH + c) * HID + jc * 128 + j);
                unsigned hi, lo; split2(v, hi, lo);
                w1h[(c * W1_S + j) >> 1] = hi;
                w1l[(c * W1_S + j) >> 1] = lo;
            }
            for (int i = tid; i < 128 * 64 / 2; i += NTHR) {
                int flat = i * 2;
                int j = flat >> 6, c = flat & 63;
                float2 v = *(const float2*)(w2g + ((size_t)layer * HID + jc * 128 + j) * CH + c);
                unsigned hi, lo; split2(v, hi, lo);
                w2h[(j * W2_S + c) >> 1] = hi;
                w2l[(j * W2_S + c) >> 1] = lo;
            }
            __syncthreads();

            // ---- GEMM1: [16 tok] x [128 j], K=64, 3-pass bf16 ----
            float d1[64];
            #pragma unroll
            for (int i = 0; i < 64; ++i) d1[i] = 0.f;
            for (int ks = 0; ks < 4; ++ks) {
                int k0 = ks * 16;
                unsigned aoff = ((tb + r15) * XN_S + k0 + colsel) * 2;
                unsigned ah[4], al[4];
                ldsm_x4(ah, smem_base + OFF_XNH + aoff);
                ldsm_x4(al, smem_base + OFF_XNL + aoff);
                #pragma unroll
                for (int ntp = 0; ntp < 8; ++ntp) {
                    unsigned boff = ((k0 + r15) * W1_S + ntp * 16 + colsel) * 2;
                    unsigned bh[4], bl[4];
                    ldsm_x4t(bh, smem_base + OFF_W1H + boff);
                    ldsm_x4t(bl, smem_base + OFF_W1L + boff);
                    mma_bf16(d1 + ntp * 8,     ah, bh[0], bh[1]);
                    mma_bf16(d1 + ntp * 8,     ah, bl[0], bl[1]);
                    mma_bf16(d1 + ntp * 8,     al, bh[0], bh[1]);
                    mma_bf16(d1 + ntp * 8 + 4, ah, bh[2], bh[3]);
                    mma_bf16(d1 + ntp * 8 + 4, ah, bl[2], bl[3]);
                    mma_bf16(d1 + ntp * 8 + 4, al, bh[2], bh[3]);
                }
            }
            // ---- epilogue: bias + gelu -> sH hi/lo (warp-local rows) ----
            {
                int r0 = tb + (lane >> 2), r1 = r0 + 8;
                int jb = (lane & 3) * 2;
                #pragma unroll
                for (int nt = 0; nt < 16; ++nt) {
                    int j0 = nt * 8 + jb;
                    float2 bv = *(const float2*)(sB1 + jc * 128 + j0);
                    float2 v0, v1;
                    v0.x = gelu_f(d1[nt * 4 + 0] + bv.x);
                    v0.y = gelu_f(d1[nt * 4 + 1] + bv.y);
                    v1.x = gelu_f(d1[nt * 4 + 2] + bv.x);
                    v1.y = gelu_f(d1[nt * 4 + 3] + bv.y);
                    unsigned hi, lo;
                    split2(v0, hi, lo);
                    hh[(r0 * H_S + j0) >> 1] = hi;
                    hl[(r0 * H_S + j0) >> 1] = lo;
                    split2(v1, hi, lo);
                    hh[(r1 * H_S + j0) >> 1] = hi;
                    hl[(r1 * H_S + j0) >> 1] = lo;
                }
            }
            __syncwarp();

            // ---- GEMM2 accumulate: [16 tok] x [64 c], K=128 chunk, 3-pass ----
            for (int ks = 0; ks < 8; ++ks) {
                int k0 = ks * 16;
                unsigned aoff = ((tb + r15) * H_S + k0 + colsel) * 2;
                unsigned ah[4], al[4];
                ldsm_x4(ah, smem_base + OFF_HH + aoff);
                ldsm_x4(al, smem_base + OFF_HL + aoff);
                #pragma unroll
                for (int ntp = 0; ntp < 4; ++ntp) {
                    unsigned boff = ((k0 + r15) * W2_S + ntp * 16 + colsel) * 2;
                    unsigned bh[4], bl[4];
                    ldsm_x4t(bh, smem_base + OFF_W2H + boff);
                    ldsm_x4t(bl, smem_base + OFF_W2L + boff);
                    mma_bf16(d2 + ntp * 8,     ah, bh[0], bh[1]);
                    mma_bf16(d2 + ntp * 8,     ah, bl[0], bl[1]);
                    mma_bf16(d2 + ntp * 8,     al, bh[0], bh[1]);
                    mma_bf16(d2 + ntp * 8 + 4, ah, bh[2], bh[3]);
                    mma_bf16(d2 + ntp * 8 + 4, ah, bl[2], bl[3]);
                    mma_bf16(d2 + ntp * 8 + 4, al, bh[2], bh[3]);
                }
            }
        }

        // ---- gated residual add into sT (warp-local rows) ----
        {
            int r0 = tb + (lane >> 2), r1 = r0 + 8;
            int cb = (lane & 3) * 2;
            int f0 = sFlag[r0], f1 = sFlag[r1];
            #pragma unroll
            for (int nt = 0; nt < 8; ++nt) {
                int c0 = nt * 8 + cb;
                float2 bv = *(const float2*)(sB2 + c0);
                if (f0) {
                    sT[r0 * ST_S + c0]     += d2[nt * 4 + 0] + bv.x;
                    sT[r0 * ST_S + c0 + 1] += d2[nt * 4 + 1] + bv.y;
                }
                if (f1) {
                    sT[r1 * ST_S + c0]     += d2[nt * 4 + 2] + bv.x;
                    sT[r1 * ST_S + c0 + 1] += d2[nt * 4 + 3] + bv.y;
                }
            }
        }
        __syncthreads();
    }

    // ---- store tile ----
    float* ob = out + (size_t)b * CH * NPIX + n0;
    for (int i = tid; i < TOKB * CH; i += NTHR) {
        int t = i & (TOKB - 1);
        int c = i >> 7;
        ob[(size_t)c * NPIX + t] = sT[t * ST_S + c];
    }
}

// ---------------- launch ----------------
extern "C" void kernel_launch(void* const* d_in, const int* in_sizes, int n_in,
                              void* d_out, int out_size) {
    const float* x    = (const float*)d_in[0];
    const float* prop = (const float*)d_in[1];
    const float* lns  = (const float*)d_in[2];
    const float* lnb  = (const float*)d_in[3];
    const float* w1   = (const float*)d_in[4];
    const float* b1   = (const float*)d_in[5];
    const float* w2   = (const float*)d_in[6];
    const float* b2   = (const float*)d_in[7];
    float* out = (float*)d_out;

    cudaFuncSetAttribute(main_kernel, cudaFuncAttributeMaxDynamicSharedMemorySize, SMEM_BYTES);

    select_kernel<<<BATCH, 1024>>>(prop);
    flags_kernel<<<BATCH, 1024>>>(prop);
    dim3 grid(NPIX / TOKB, BATCH);
    main_kernel<<<grid, NTHR, SMEM_BYTES>>>(x, lns, lnb, w1, b1, w2, b2, out);
}

// round 3
// speedup vs baseline: 4.6288x; 1.7452x over previous
#include <cuda_runtime.h>
#include <cuda_bf16.h>
#include <math.h>

#define BATCH 16
#define CH    64
#define NPIX  25600          // 160*160
#define HID   256
#define KSEL  20480          // ceil(25600*0.8)
#define TOKB  128            // tokens per block
#define NTHR  256            // 8 warps

#define ST_S  68             // sT fp32 row stride (272B)
#define W1_S  136            // bf16 elements per row (272B), chunk rows=64
#define W2_S  72             // bf16 elements per row (144B), chunk rows=128

// smem byte offsets
#define OFF_T    0            // 128*68*4  = 34816
#define OFF_W1H  34816        // 17408
#define OFF_W1L  52224        // 17408
#define OFF_W2H  69632        // 18432
#define OFF_W2L  88064        // 18432
#define OFF_B1   106496       // 2*256*4 = 2048
#define OFF_B2   108544       // 2*64*4  = 512
#define OFF_LS   109056       // 512
#define OFF_LB   109568       // 512
#define OFF_FLAG 110080       // 128*4   = 512
#define SMEM_BYTES 110592

// ---------------- static scratch ----------------
__device__ unsigned      g_thresh[BATCH];
__device__ int           g_ties[BATCH];
__device__ unsigned char g_flags[BATCH * NPIX];
// pre-split weights, already in smem tile layout (chunk = layer*2 + jc)
__device__ unsigned short g_w1h[4 * 64 * W1_S];
__device__ unsigned short g_w1l[4 * 64 * W1_S];
__device__ unsigned short g_w2h[4 * 128 * W2_S];
__device__ unsigned short g_w2l[4 * 128 * W2_S];

__device__ __forceinline__ unsigned fkey(float f) {
    unsigned u = __float_as_uint(f);
    return (u & 0x80000000u) ? ~u : (u | 0x80000000u);
}

__device__ __forceinline__ float gelu_f(float v) {
    float inner = 0.7978845608028654f * (v + 0.044715f * v * v * v);
    float t;
    asm("tanh.approx.f32 %0, %1;" : "=f"(t) : "f"(inner));
    return 0.5f * v * (1.0f + t);
}

__device__ __forceinline__ void split2(float2 v, unsigned &hi, unsigned &lo) {
    __nv_bfloat162 h = __float22bfloat162_rn(v);
    float2 r;
    r.x = v.x - __bfloat162float(h.x);
    r.y = v.y - __bfloat162float(h.y);
    __nv_bfloat162 l = __float22bfloat162_rn(r);
    hi = *(unsigned*)&h;
    lo = *(unsigned*)&l;
}

__device__ __forceinline__ void ldsm_x4t(unsigned r[4], unsigned addr) {
    asm volatile("ldmatrix.sync.aligned.m8n8.x4.trans.shared.b16 {%0,%1,%2,%3}, [%4];"
                 : "=r"(r[0]), "=r"(r[1]), "=r"(r[2]), "=r"(r[3]) : "r"(addr));
}
__device__ __forceinline__ void mma_bf16(float* d, const unsigned* a, unsigned b0, unsigned b1) {
    asm volatile("mma.sync.aligned.m16n8k16.row.col.f32.bf16.bf16.f32 "
                 "{%0,%1,%2,%3}, {%4,%5,%6,%7}, {%8,%9}, {%0,%1,%2,%3};"
                 : "+f"(d[0]), "+f"(d[1]), "+f"(d[2]), "+f"(d[3])
                 : "r"(a[0]), "r"(a[1]), "r"(a[2]), "r"(a[3]), "r"(b0), "r"(b1));
}
__device__ __forceinline__ void cp16(unsigned dst, const void* src) {
    asm volatile("cp.async.cg.shared.global [%0], [%1], 16;" :: "r"(dst), "l"(src));
}

// ---------------- kernel 0: pre-split weights into bf16 hi/lo (smem layout) --------
__global__ void prep_kernel(const float* __restrict__ w1, const float* __restrict__ w2) {
    int idx = blockIdx.x * blockDim.x + threadIdx.x;
    if (idx >= 2 * CH * HID) return;
    int layer = idx >> 14;
    int rem = idx & 16383;
    // w1: [layer][c][j]
    {
        int c = rem >> 8, j = rem & 255;
        float v = w1[idx];
        __nv_bfloat16 h = __float2bfloat16(v);
        __nv_bfloat16 l = __float2bfloat16(v - __bfloat162float(h));
        int off = (layer * 2 + (j >> 7)) * 64 * W1_S + c * W1_S + (j & 127);
        g_w1h[off] = *(unsigned short*)&h;
        g_w1l[off] = *(unsigned short*)&l;
    }
    // w2: [layer][j][c]
    {
        int j = rem >> 6, c = rem & 63;
        float v = w2[idx];
        __nv_bfloat16 h = __float2bfloat16(v);
        __nv_bfloat16 l = __float2bfloat16(v - __bfloat162float(h));
        int off = (layer * 2 + (j >> 7)) * 128 * W2_S + (j & 127) * W2_S + c;
        g_w2h[off] = *(unsigned short*)&h;
        g_w2l[off] = *(unsigned short*)&l;
    }
}

// ---------------- kernel 1: per-batch radix select (K-th largest) ----------------
__global__ void select_kernel(const float* __restrict__ prop) {
    int b = blockIdx.x;
    const float4* p4 = (const float4*)(prop + (size_t)b * NPIX);
    __shared__ unsigned hist[256];
    __shared__ unsigned s_prefix;
    __shared__ int s_k;
    if (threadIdx.x == 0) { s_prefix = 0u; s_k = KSEL; }
    __syncthreads();

    for (int pass = 3; pass >= 0; --pass) {
        int shift = pass * 8;
        if (threadIdx.x < 256) hist[threadIdx.x] = 0u;
        __syncthreads();
        unsigned prefix = s_prefix;
        unsigned highmask = (pass == 3) ? 0u : (0xFFFFFFFFu << (shift + 8));
        for (int i = threadIdx.x; i < NPIX / 4; i += 1024) {
            float4 v = p4[i];
            unsigned u0 = fkey(v.x), u1 = fkey(v.y), u2 = fkey(v.z), u3 = fkey(v.w);
            if ((u0 & highmask) == prefix) atomicAdd(&hist[(u0 >> shift) & 255u], 1u);
            if ((u1 & highmask) == prefix) atomicAdd(&hist[(u1 >> shift) & 255u], 1u);
            if ((u2 & highmask) == prefix) atomicAdd(&hist[(u2 >> shift) & 255u], 1u);
            if ((u3 & highmask) == prefix) atomicAdd(&hist[(u3 >> shift) & 255u], 1u);
        }
        __syncthreads();
        if (threadIdx.x == 0) {
            int k = s_k;
            unsigned cum = 0;
            for (int d = 255; d >= 0; --d) {
                unsigned cnt = hist[d];
                if ((unsigned)k <= cum + cnt) {
                    s_prefix = prefix | ((unsigned)d << shift);
                    s_k = k - (int)cum;
                    break;
                }
                cum += cnt;
            }
        }
        __syncthreads();
    }
    if (threadIdx.x == 0) {
        g_thresh[b] = s_prefix;
        g_ties[b]   = s_k;
    }
}

// ---------------- kernel 2: selected-token flags (index-ordered ties) ----------------
__global__ void flags_kernel(const float* __restrict__ prop) {
    int b = blockIdx.x;
    const float4* p4 = (const float4*)(prop + (size_t)b * NPIX);
    unsigned T = g_thresh[b];
    int ties = g_ties[b];
    __shared__ int s_carry;
    __shared__ int warp_sums[32];
    int tid = threadIdx.x;
    int lane = tid & 31, w = tid >> 5;
    if (tid == 0) s_carry = 0;
    __syncthreads();

    for (int base = 0; base < NPIX / 4; base += 1024) {
        int i = base + tid;
        float4 v = (i < NPIX / 4) ? p4[i] : make_float4(0, 0, 0, 0);
        unsigned u[4] = {fkey(v.x), fkey(v.y), fkey(v.z), fkey(v.w)};
        int eq[4], gt[4], cnt = 0;
        #pragma unroll
        for (int kq = 0; kq < 4; ++kq) {
            gt[kq] = (i < NPIX / 4) && (u[kq] > T);
            eq[kq] = (i < NPIX / 4) && (u[kq] == T);
            cnt += eq[kq];
        }
        int sc = cnt;
        #pragma unroll
        for (int o = 1; o < 32; o <<= 1) {
            int vv = __shfl_up_sync(0xffffffffu, sc, o);
            if (lane >= o) sc += vv;
        }
        if (lane == 31) warp_sums[w] = sc;
        __syncthreads();
        int woff = 0;
        for (int xw = 0; xw < w; ++xw) woff += warp_sums[xw];
        int rank = s_carry + woff + (sc - cnt);
        if (i < NPIX / 4) {
            uchar4 fo;
            fo.x = (unsigned char)(gt[0] || (eq[0] && rank < ties)); rank += eq[0];
            fo.y = (unsigned char)(gt[1] || (eq[1] && rank < ties)); rank += eq[1];
            fo.z = (unsigned char)(gt[2] || (eq[2] && rank < ties)); rank += eq[2];
            fo.w = (unsigned char)(gt[3] || (eq[3] && rank < ties));
            *(uchar4*)(g_flags + (size_t)b * NPIX + i * 4) = fo;
        }
        __syncthreads();
        if (tid == 0) {
            int tot = 0;
            for (int xw = 0; xw < 32; ++xw) tot += warp_sums[xw];
            s_carry += tot;
        }
        __syncthreads();
    }
}

// ---------------- kernel 3: fused LN + MLP, register-resident fragments ----------
__global__ void __launch_bounds__(NTHR, 2)
main_kernel(const float* __restrict__ x,
            const float* __restrict__ lnscale, const float* __restrict__ lnbias,
            const float* __restrict__ b1g, const float* __restrict__ b2g,
            float* __restrict__ out) {
    extern __shared__ char sm[];
    float* sT  = (float*)(sm + OFF_T);
    float* sB1 = (float*)(sm + OFF_B1);
    float* sB2 = (float*)(sm + OFF_B2);
    float* sLS = (float*)(sm + OFF_LS);
    float* sLB = (float*)(sm + OFF_LB);
    int*   sFlag = (int*)(sm + OFF_FLAG);
    unsigned smem_base = (unsigned)__cvta_generic_to_shared(sm);

    int tid = threadIdx.x;
    int lane = tid & 31, w = tid >> 5;
    int tb = w * 16;
    int b = blockIdx.y, n0 = blockIdx.x * TOKB;

    int r = lane >> 2;           // fragment row within 8
    int c2 = (lane & 3) * 2;     // fragment col pair
    int r15 = lane & 15;
    int colsel = ((lane >> 4) & 1) * 8;
    int row0 = tb + r, row1 = row0 + 8;

    // ---- load x tile: sT[t][c], params, flags ----
    const float* xb = x + (size_t)b * CH * NPIX + n0;
    for (int i = tid; i < TOKB * CH; i += NTHR) {
        int t = i & (TOKB - 1);
        int c = i >> 7;
        sT[t * ST_S + c] = xb[(size_t)c * NPIX + t];
    }
    for (int i = tid; i < 2 * HID; i += NTHR) sB1[i] = b1g[i];
    if (tid < 2 * CH) {
        sB2[tid] = b2g[tid];
        sLS[tid] = lnscale[tid];
        sLB[tid] = lnbias[tid];
    }
    if (tid < TOKB) sFlag[tid] = g_flags[(size_t)b * NPIX + n0 + tid];
    __syncthreads();

    for (int layer = 0; layer < 2; ++layer) {
        // ---- LN stats (warp-local): 2 lanes per token ----
        float mu, rs;
        {
            int t = tb + (lane >> 1), half = lane & 1;
            const float* rowp = sT + t * ST_S + half * 32;
            float s = 0.f, s2 = 0.f;
            #pragma unroll
            for (int k = 0; k < 32; k += 4) {
                float4 v = *(const float4*)(rowp + k);
                s  += v.x + v.y + v.z + v.w;
                s2 += v.x * v.x + v.y * v.y + v.z * v.z + v.w * v.w;
            }
            s  += __shfl_xor_sync(0xffffffffu, s, 1);
            s2 += __shfl_xor_sync(0xffffffffu, s2, 1);
            mu = s * (1.f / 64.f);
            float var = s2 * (1.f / 64.f) - mu * mu;
            rs = rsqrtf(var + 1e-5f);
        }
        float mu0 = __shfl_sync(0xffffffffu, mu, r << 1);
        float rs0 = __shfl_sync(0xffffffffu, rs, r << 1);
        float mu1 = __shfl_sync(0xffffffffu, mu, (r << 1) + 16);
        float rs1 = __shfl_sync(0xffffffffu, rs, (r << 1) + 16);

        // ---- build GEMM1 A-fragments (Xn) in registers, hi/lo ----
        unsigned aXh[16], aXl[16];
        #pragma unroll
        for (int kt = 0; kt < 4; ++kt) {
            int cA = kt * 16 + c2;
            float2 lsA = *(const float2*)(sLS + layer * 64 + cA);
            float2 lbA = *(const float2*)(sLB + layer * 64 + cA);
            float2 lsB = *(const float2*)(sLS + layer * 64 + cA + 8);
            float2 lbB = *(const float2*)(sLB + layer * 64 + cA + 8);
            float2 v;
            v = *(const float2*)(sT + row0 * ST_S + cA);
            v.x = (v.x - mu0) * rs0 * lsA.x + lbA.x;
            v.y = (v.y - mu0) * rs0 * lsA.y + lbA.y;
            split2(v, aXh[kt * 4 + 0], aXl[kt * 4 + 0]);
            v = *(const float2*)(sT + row1 * ST_S + cA);
            v.x = (v.x - mu1) * rs1 * lsA.x + lbA.x;
            v.y = (v.y - mu1) * rs1 * lsA.y + lbA.y;
            split2(v, aXh[kt * 4 + 1], aXl[kt * 4 + 1]);
            v = *(const float2*)(sT + row0 * ST_S + cA + 8);
            v.x = (v.x - mu0) * rs0 * lsB.x + lbB.x;
            v.y = (v.y - mu0) * rs0 * lsB.y + lbB.y;
            split2(v, aXh[kt * 4 + 2], aXl[kt * 4 + 2]);
            v = *(const float2*)(sT + row1 * ST_S + cA + 8);
            v.x = (v.x - mu1) * rs1 * lsB.x + lbB.x;
            v.y = (v.y - mu1) * rs1 * lsB.y + lbB.y;
            split2(v, aXh[kt * 4 + 3], aXl[kt * 4 + 3]);
        }

        float d2[32];
        #pragma unroll
        for (int i = 0; i < 32; ++i) d2[i] = 0.f;

        for (int jc = 0; jc < 2; ++jc) {
            int ch = layer * 2 + jc;
            __syncthreads();   // previous chunk fully consumed
            // ---- stage pre-split weight chunk via cp.async ----
            {
                const char* g1h = (const char*)(g_w1h + ch * 64 * W1_S);
                const char* g1l = (const char*)(g_w1l + ch * 64 * W1_S);
                const char* g2h = (const char*)(g_w2h + ch * 128 * W2_S);
                const char* g2l = (const char*)(g_w2l + ch * 128 * W2_S);
                for (int i = tid * 16; i < 64 * W1_S * 2; i += NTHR * 16) {
                    cp16(smem_base + OFF_W1H + i, g1h + i);
                    cp16(smem_base + OFF_W1L + i, g1l + i);
                }
                for (int i = tid * 16; i < 128 * W2_S * 2; i += NTHR * 16) {
                    cp16(smem_base + OFF_W2H + i, g2h + i);
                    cp16(smem_base + OFF_W2L + i, g2l + i);
                }
                asm volatile("cp.async.commit_group;");
                asm volatile("cp.async.wait_group 0;");
            }
            __syncthreads();

            for (int jg = 0; jg < 8; ++jg) {
                // ---- GEMM1: d1[16 tok x 16 j], K=64, 3-pass ----
                float d1[8];
                #pragma unroll
                for (int i = 0; i < 8; ++i) d1[i] = 0.f;
                #pragma unroll
                for (int kt = 0; kt < 4; ++kt) {
                    unsigned bh[4], bl[4];
                    unsigned boff = (unsigned)((kt * 16 + r15) * W1_S + jg * 16 + colsel) * 2;
                    ldsm_x4t(bh, smem_base + OFF_W1H + boff);
                    ldsm_x4t(bl, smem_base + OFF_W1L + boff);
                    mma_bf16(d1,     aXh + kt * 4, bh[0], bh[1]);
                    mma_bf16(d1,     aXh + kt * 4, bl[0], bl[1]);
                    mma_bf16(d1,     aXl + kt * 4, bh[0], bh[1]);
                    mma_bf16(d1 + 4, aXh + kt * 4, bh[2], bh[3]);
                    mma_bf16(d1 + 4, aXh + kt * 4, bl[2], bl[3]);
                    mma_bf16(d1 + 4, aXl + kt * 4, bh[2], bh[3]);
                }
                // ---- epilogue in regs: bias + gelu + split -> GEMM2 A frags ----
                unsigned a2h[4], a2l[4];
                {
                    int j0 = jc * 128 + jg * 16;
                    const float* bptr = sB1 + layer * HID + j0;
                    float2 b0 = *(const float2*)(bptr + c2);
                    float2 b8 = *(const float2*)(bptr + 8 + c2);
                    float2 v;
                    v.x = gelu_f(d1[0] + b0.x); v.y = gelu_f(d1[1] + b0.y); split2(v, a2h[0], a2l[0]);
                    v.x = gelu_f(d1[2] + b0.x); v.y = gelu_f(d1[3] + b0.y); split2(v, a2h[1], a2l[1]);
                    v.x = gelu_f(d1[4] + b8.x); v.y = gelu_f(d1[5] + b8.y); split2(v, a2h[2], a2l[2]);
                    v.x = gelu_f(d1[6] + b8.x); v.y = gelu_f(d1[7] + b8.y); split2(v, a2h[3], a2l[3]);
                }
                // ---- GEMM2 partial: k-tile = this jg, N=64, 3-pass ----
                #pragma unroll
                for (int np = 0; np < 4; ++np) {
                    unsigned bh[4], bl[4];
                    unsigned boff = (unsigned)((jg * 16 + r15) * W2_S + np * 16 + colsel) * 2;
                    ldsm_x4t(bh, smem_base + OFF_W2H + boff);
                    ldsm_x4t(bl, smem_base + OFF_W2L + boff);
                    mma_bf16(d2 + np * 8,     a2h, bh[0], bh[1]);
                    mma_bf16(d2 + np * 8,     a2h, bl[0], bl[1]);
                    mma_bf16(d2 + np * 8,     a2l, bh[0], bh[1]);
                    mma_bf16(d2 + np * 8 + 4, a2h, bh[2], bh[3]);
                    mma_bf16(d2 + np * 8 + 4, a2h, bl[2], bl[3]);
                    mma_bf16(d2 + np * 8 + 4, a2l, bh[2], bh[3]);
                }
            }
        }

        // ---- gated residual add into sT (warp-local rows) ----
        {
            int f0 = sFlag[row0], f1 = sFlag[row1];
            #pragma unroll
            for (int nt = 0; nt < 8; ++nt) {
                int c0 = nt * 8 + c2;
                float2 bv = *(const float2*)(sB2 + layer * 64 + c0);
                if (f0) {
                    sT[row0 * ST_S + c0]     += d2[nt * 4 + 0] + bv.x;
                    sT[row0 * ST_S + c0 + 1] += d2[nt * 4 + 1] + bv.y;
                }
                if (f1) {
                    sT[row1 * ST_S + c0]     += d2[nt * 4 + 2] + bv.x;
                    sT[row1 * ST_S + c0 + 1] += d2[nt * 4 + 3] + bv.y;
                }
            }
        }
        __syncwarp();
    }

    // ---- store tile ----
    __syncthreads();
    float* ob = out + (size_t)b * CH * NPIX + n0;
    for (int i = tid; i < TOKB * CH; i += NTHR) {
        int t = i & (TOKB - 1);
        int c = i >> 7;
        ob[(size_t)c * NPIX + t] = sT[t * ST_S + c];
    }
}

// ---------------- launch ----------------
extern "C" void kernel_launch(void* const* d_in, const int* in_sizes, int n_in,
                              void* d_out, int out_size) {
    const float* x    = (const float*)d_in[0];
    const float* prop = (const float*)d_in[1];
    const float* lns  = (const float*)d_in[2];
    const float* lnb  = (const float*)d_in[3];
    const float* w1   = (const float*)d_in[4];
    const float* b1   = (const float*)d_in[5];
    const float* w2   = (const float*)d_in[6];
    const float* b2   = (const float*)d_in[7];
    float* out = (float*)d_out;

    cudaFuncSetAttribute(main_kernel, cudaFuncAttributeMaxDynamicSharedMemorySize, SMEM_BYTES);

    prep_kernel<<<64, 512>>>(w1, w2);
    select_kernel<<<BATCH, 1024>>>(prop);
    flags_kernel<<<BATCH, 1024>>>(prop);
    dim3 grid(NPIX / TOKB, BATCH);
    main_kernel<<<grid, NTHR, SMEM_BYTES>>>(x, lns, lnb, b1, b2, out);
}

// round 4
// speedup vs baseline: 6.0138x; 1.2992x over previous
#include <cuda_runtime.h>
#include <cuda_fp16.h>
#include <math.h>

#define BATCH 16
#define CH    64
#define NPIX  25600          // 160*160
#define HID   256
#define KSEL  20480          // ceil(25600*0.8)
#define TOKB  128            // tokens per block
#define NTHR  256            // 8 warps

#define ST_S  68             // sT fp32 row stride (272B)
#define W1_S  136            // fp16 elements per row (272B), chunk rows=64
#define W2_S  72             // fp16 elements per row (144B), chunk rows=128

// smem byte offsets (main kernel)
#define OFF_T    0            // 128*68*4  = 34816
#define OFF_W    34816        // two chunk buffers, each 35840 (W1 17408 + W2 18432)
#define BUFB     35840
#define OFF_B1   106496       // 2*256*4 = 2048
#define OFF_B2   108544       // 2*64*4  = 512
#define OFF_LS   109056       // 512
#define OFF_LB   109568       // 512
#define OFF_FLAG 110080       // 128*4   = 512
#define SMEM_BYTES 110592

// ---------------- static scratch ----------------
__device__ unsigned      g_thresh[BATCH];
__device__ int           g_ties[BATCH];
__device__ int           g_eqcnt[BATCH];
__device__ int           g_eqidx[BATCH * NPIX];
__device__ unsigned char g_flags[BATCH * NPIX];
// pre-converted fp16 weights in smem tile layout (chunk = layer*2 + jc)
__device__ unsigned short g_w1[4 * 64 * W1_S];
__device__ unsigned short g_w2[4 * 128 * W2_S];

__device__ __forceinline__ unsigned fkey(float f) {
    unsigned u = __float_as_uint(f);
    return (u & 0x80000000u) ? ~u : (u | 0x80000000u);
}

__device__ __forceinline__ float gelu_f(float v) {
    float inner = 0.7978845608028654f * (v + 0.044715f * v * v * v);
    float t;
    asm("tanh.approx.f32 %0, %1;" : "=f"(t) : "f"(inner));
    return 0.5f * v * (1.0f + t);
}

// split fp32 pair into hi/lo fp16 pairs (packed u32); hi+lo == v to ~2^-22
__device__ __forceinline__ void split2h(float2 v, unsigned &hi, unsigned &lo) {
    __half2 h = __float22half2_rn(v);
    float2 r;
    r.x = v.x - __half2float(__low2half(h));
    r.y = v.y - __half2float(__high2half(h));
    __half2 l = __float22half2_rn(r);
    hi = *(unsigned*)&h;
    lo = *(unsigned*)&l;
}

__device__ __forceinline__ void ldsm_x4t(unsigned r[4], unsigned addr) {
    asm volatile("ldmatrix.sync.aligned.m8n8.x4.trans.shared.b16 {%0,%1,%2,%3}, [%4];"
                 : "=r"(r[0]), "=r"(r[1]), "=r"(r[2]), "=r"(r[3]) : "r"(addr));
}
__device__ __forceinline__ void mma_f16(float* d, const unsigned* a, unsigned b0, unsigned b1) {
    asm volatile("mma.sync.aligned.m16n8k16.row.col.f32.f16.f16.f32 "
                 "{%0,%1,%2,%3}, {%4,%5,%6,%7}, {%8,%9}, {%0,%1,%2,%3};"
                 : "+f"(d[0]), "+f"(d[1]), "+f"(d[2]), "+f"(d[3])
                 : "r"(a[0]), "r"(a[1]), "r"(a[2]), "r"(a[3]), "r"(b0), "r"(b1));
}
__device__ __forceinline__ void cp16(unsigned dst, const void* src) {
    asm volatile("cp.async.cg.shared.global [%0], [%1], 16;" :: "r"(dst), "l"(src));
}

// ---------------- kernel 0: pre-convert weights to fp16 (smem tile layout) --------
__global__ void prep_kernel(const float* __restrict__ w1, const float* __restrict__ w2) {
    int idx = blockIdx.x * blockDim.x + threadIdx.x;
    if (idx >= 2 * CH * HID) return;
    int layer = idx >> 14;
    int rem = idx & 16383;
    {   // w1: [layer][c][j]
        int c = rem >> 8, j = rem & 255;
        __half h = __float2half_rn(w1[idx]);
        int off = (layer * 2 + (j >> 7)) * 64 * W1_S + c * W1_S + (j & 127);
        g_w1[off] = *(unsigned short*)&h;
    }
    {   // w2: [layer][j][c]
        int j = rem >> 6, c = rem & 63;
        __half h = __float2half_rn(w2[idx]);
        int off = (layer * 2 + (j >> 7)) * 128 * W2_S + (j & 127) * W2_S + c;
        g_w2[off] = *(unsigned short*)&h;
    }
}

// ---------------- kernel 1: per-batch radix select (keys cached in smem) ----------
__global__ void select_kernel(const float* __restrict__ prop) {
    int b = blockIdx.x;
    const float* p = prop + (size_t)b * NPIX;
    extern __shared__ unsigned dyn[];
    unsigned* skey = dyn;              // 25600
    unsigned* hist = dyn + NPIX;       // 256
    __shared__ unsigned s_prefix;
    __shared__ int s_k;
    if (threadIdx.x == 0) { s_prefix = 0u; s_k = KSEL; g_eqcnt[b] = 0; }
    for (int i = threadIdx.x; i < NPIX; i += 1024) skey[i] = fkey(p[i]);
    __syncthreads();

    for (int pass = 3; pass >= 0; --pass) {
        int shift = pass * 8;
        if (threadIdx.x < 256) hist[threadIdx.x] = 0u;
        __syncthreads();
        unsigned prefix = s_prefix;
        unsigned highmask = (pass == 3) ? 0u : (0xFFFFFFFFu << (shift + 8));
        for (int i = threadIdx.x; i < NPIX; i += 1024) {
            unsigned u = skey[i];
            if ((u & highmask) == prefix)
                atomicAdd(&hist[(u >> shift) & 255u], 1u);
        }
        __syncthreads();
        if (threadIdx.x == 0) {
            int k = s_k;
            unsigned cum = 0;
            for (int d = 255; d >= 0; --d) {
                unsigned cnt = hist[d];
                if ((unsigned)k <= cum + cnt) {
                    s_prefix = prefix | ((unsigned)d << shift);
                    s_k = k - (int)cum;
                    break;
                }
                cum += cnt;
            }
        }
        __syncthreads();
    }
    if (threadIdx.x == 0) {
        g_thresh[b] = s_prefix;
        g_ties[b]   = s_k;
    }
}

// ---------------- kernel 2a: grid-parallel gt flags + eq capture ----------------
__global__ void flags1_kernel(const float* __restrict__ prop) {
    int b = blockIdx.y;
    int i = blockIdx.x * 1024 + threadIdx.x;
    unsigned T = g_thresh[b];
    unsigned u = fkey(prop[(size_t)b * NPIX + i]);
    unsigned char f = (u > T) ? 1 : 0;
    if (u == T) {
        int s = atomicAdd(&g_eqcnt[b], 1);
        g_eqidx[(size_t)b * NPIX + s] = i;
    }
    g_flags[(size_t)b * NPIX + i] = f;
}

// ---------------- kernel 2b: tie fixup (n expected ~1) ----------------
__global__ void flags2_kernel() {
    int b = blockIdx.x;
    int n = g_eqcnt[b];
    int ties = g_ties[b];
    for (int e = threadIdx.x; e < n; e += 256) {
        int idx = g_eqidx[(size_t)b * NPIX + e];
        int rank = 0;
        for (int q = 0; q < n; ++q)
            rank += (g_eqidx[(size_t)b * NPIX + q] < idx) ? 1 : 0;
        if (rank < ties) g_flags[(size_t)b * NPIX + idx] = 1;
    }
}

// ---------------- kernel 3: fused LN + MLP, fp16 2-pass, double-buffered weights ----
__global__ void __launch_bounds__(NTHR, 2)
main_kernel(const float* __restrict__ x,
            const float* __restrict__ lnscale, const float* __restrict__ lnbias,
            const float* __restrict__ b1g, const float* __restrict__ b2g,
            float* __restrict__ out) {
    extern __shared__ char sm[];
    float* sT  = (float*)(sm + OFF_T);
    float* sB1 = (float*)(sm + OFF_B1);
    float* sB2 = (float*)(sm + OFF_B2);
    float* sLS = (float*)(sm + OFF_LS);
    float* sLB = (float*)(sm + OFF_LB);
    int*   sFlag = (int*)(sm + OFF_FLAG);
    unsigned smem_base = (unsigned)__cvta_generic_to_shared(sm);

    int tid = threadIdx.x;
    int lane = tid & 31, w = tid >> 5;
    int tb = w * 16;
    int b = blockIdx.y, n0 = blockIdx.x * TOKB;

    int r = lane >> 2;           // fragment row within 8
    int c2 = (lane & 3) * 2;     // fragment col pair
    int r15 = lane & 15;
    int colsel = ((lane >> 4) & 1) * 8;
    int row0 = tb + r, row1 = row0 + 8;

    // ---- stage chunk 0 weights (async) ----
    {
        const char* s1 = (const char*)g_w1;
        const char* s2 = (const char*)g_w2;
        unsigned dst = smem_base + OFF_W;
        for (int i = tid * 16; i < 64 * W1_S * 2; i += NTHR * 16) cp16(dst + i, s1 + i);
        for (int i = tid * 16; i < 128 * W2_S * 2; i += NTHR * 16) cp16(dst + 17408 + i, s2 + i);
        asm volatile("cp.async.commit_group;");
    }

    // ---- load x tile: sT[t][c], params, flags ----
    const float* xb = x + (size_t)b * CH * NPIX + n0;
    for (int i = tid; i < TOKB * CH; i += NTHR) {
        int t = i & (TOKB - 1);
        int c = i >> 7;
        sT[t * ST_S + c] = xb[(size_t)c * NPIX + t];
    }
    for (int i = tid; i < 2 * HID; i += NTHR) sB1[i] = b1g[i];
    if (tid < 2 * CH) {
        sB2[tid] = b2g[tid];
        sLS[tid] = lnscale[tid];
        sLB[tid] = lnbias[tid];
    }
    if (tid < TOKB) sFlag[tid] = g_flags[(size_t)b * NPIX + n0 + tid];
    __syncthreads();

    for (int layer = 0; layer < 2; ++layer) {
        // ---- LN stats (warp-local): 2 lanes per token ----
        float mu, rs;
        {
            int t = tb + (lane >> 1), half = lane & 1;
            const float* rowp = sT + t * ST_S + half * 32;
            float s = 0.f, s2 = 0.f;
            #pragma unroll
            for (int k = 0; k < 32; k += 4) {
                float4 v = *(const float4*)(rowp + k);
                s  += v.x + v.y + v.z + v.w;
                s2 += v.x * v.x + v.y * v.y + v.z * v.z + v.w * v.w;
            }
            s  += __shfl_xor_sync(0xffffffffu, s, 1);
            s2 += __shfl_xor_sync(0xffffffffu, s2, 1);
            mu = s * (1.f / 64.f);
            float var = s2 * (1.f / 64.f) - mu * mu;
            rs = rsqrtf(var + 1e-5f);
        }
        float mu0 = __shfl_sync(0xffffffffu, mu, r << 1);
        float rs0 = __shfl_sync(0xffffffffu, rs, r << 1);
        float mu1 = __shfl_sync(0xffffffffu, mu, (r << 1) + 16);
        float rs1 = __shfl_sync(0xffffffffu, rs, (r << 1) + 16);

        // ---- build GEMM1 A-fragments (Xn) in registers, fp16 hi/lo ----
        unsigned aXh[16], aXl[16];
        #pragma unroll
        for (int kt = 0; kt < 4; ++kt) {
            int cA = kt * 16 + c2;
            float2 lsA = *(const float2*)(sLS + layer * 64 + cA);
            float2 lbA = *(const float2*)(sLB + layer * 64 + cA);
            float2 lsB = *(const float2*)(sLS + layer * 64 + cA + 8);
            float2 lbB = *(const float2*)(sLB + layer * 64 + cA + 8);
            float2 v;
            v = *(const float2*)(sT + row0 * ST_S + cA);
            v.x = (v.x - mu0) * rs0 * lsA.x + lbA.x;
            v.y = (v.y - mu0) * rs0 * lsA.y + lbA.y;
            split2h(v, aXh[kt * 4 + 0], aXl[kt * 4 + 0]);
            v = *(const float2*)(sT + row1 * ST_S + cA);
            v.x = (v.x - mu1) * rs1 * lsA.x + lbA.x;
            v.y = (v.y - mu1) * rs1 * lsA.y + lbA.y;
            split2h(v, aXh[kt * 4 + 1], aXl[kt * 4 + 1]);
            v = *(const float2*)(sT + row0 * ST_S + cA + 8);
            v.x = (v.x - mu0) * rs0 * lsB.x + lbB.x;
            v.y = (v.y - mu0) * rs0 * lsB.y + lbB.y;
            split2h(v, aXh[kt * 4 + 2], aXl[kt * 4 + 2]);
            v = *(const float2*)(sT + row1 * ST_S + cA + 8);
            v.x = (v.x - mu1) * rs1 * lsB.x + lbB.x;
            v.y = (v.y - mu1) * rs1 * lsB.y + lbB.y;
            split2h(v, aXh[kt * 4 + 3], aXl[kt * 4 + 3]);
        }

        float d2[32];
        #pragma unroll
        for (int i = 0; i < 32; ++i) d2[i] = 0.f;

        for (int jc = 0; jc < 2; ++jc) {
            int ch = layer * 2 + jc;
            int buf = ch & 1;
            unsigned wbase = smem_base + OFF_W + buf * BUFB;

            // ---- prefetch next chunk into other buffer ----
            if (ch + 1 < 4) {
                int nc = ch + 1;
                const char* s1 = (const char*)(g_w1 + nc * 64 * W1_S);
                const char* s2 = (const char*)(g_w2 + nc * 128 * W2_S);
                unsigned dst = smem_base + OFF_W + (buf ^ 1) * BUFB;
                for (int i = tid * 16; i < 64 * W1_S * 2; i += NTHR * 16) cp16(dst + i, s1 + i);
                for (int i = tid * 16; i < 128 * W2_S * 2; i += NTHR * 16) cp16(dst + 17408 + i, s2 + i);
                asm volatile("cp.async.commit_group;");
                asm volatile("cp.async.wait_group 1;");
            } else {
                asm volatile("cp.async.wait_group 0;");
            }
            __syncthreads();   // current chunk weights visible to all warps

            for (int jg = 0; jg < 8; ++jg) {
                // ---- GEMM1: d1[16 tok x 16 j], K=64, 2-pass fp16 ----
                float d1[8];
                #pragma unroll
                for (int i = 0; i < 8; ++i) d1[i] = 0.f;
                #pragma unroll
                for (int kt = 0; kt < 4; ++kt) {
                    unsigned bh[4];
                    unsigned boff = (unsigned)((kt * 16 + r15) * W1_S + jg * 16 + colsel) * 2;
                    ldsm_x4t(bh, wbase + boff);
                    mma_f16(d1,     aXh + kt * 4, bh[0], bh[1]);
                    mma_f16(d1,     aXl + kt * 4, bh[0], bh[1]);
                    mma_f16(d1 + 4, aXh + kt * 4, bh[2], bh[3]);
                    mma_f16(d1 + 4, aXl + kt * 4, bh[2], bh[3]);
                }
                // ---- epilogue in regs: bias + gelu + split -> GEMM2 A frags ----
                unsigned a2h[4], a2l[4];
                {
                    int j0 = jc * 128 + jg * 16;
                    const float* bptr = sB1 + layer * HID + j0;
                    float2 b0 = *(const float2*)(bptr + c2);
                    float2 b8 = *(const float2*)(bptr + 8 + c2);
                    float2 v;
                    v.x = gelu_f(d1[0] + b0.x); v.y = gelu_f(d1[1] + b0.y); split2h(v, a2h[0], a2l[0]);
                    v.x = gelu_f(d1[2] + b0.x); v.y = gelu_f(d1[3] + b0.y); split2h(v, a2h[1], a2l[1]);
                    v.x = gelu_f(d1[4] + b8.x); v.y = gelu_f(d1[5] + b8.y); split2h(v, a2h[2], a2l[2]);
                    v.x = gelu_f(d1[6] + b8.x); v.y = gelu_f(d1[7] + b8.y); split2h(v, a2h[3], a2l[3]);
                }
                // ---- GEMM2 partial: k-tile = this jg, N=64, 2-pass fp16 ----
                #pragma unroll
                for (int np = 0; np < 4; ++np) {
                    unsigned bh[4];
                    unsigned boff = (unsigned)((jg * 16 + r15) * W2_S + np * 16 + colsel) * 2;
                    ldsm_x4t(bh, wbase + 17408 + boff);
                    mma_f16(d2 + np * 8,     a2h, bh[0], bh[1]);
                    mma_f16(d2 + np * 8,     a2l, bh[0], bh[1]);
                    mma_f16(d2 + np * 8 + 4, a2h, bh[2], bh[3]);
                    mma_f16(d2 + np * 8 + 4, a2l, bh[2], bh[3]);
                }
            }
            __syncthreads();   // all warps done with this buffer before next overwrite
        }

        // ---- gated residual add into sT (warp-local rows) ----
        {
            int f0 = sFlag[row0], f1 = sFlag[row1];
            #pragma unroll
            for (int nt = 0; nt < 8; ++nt) {
                int c0 = nt * 8 + c2;
                float2 bv = *(const float2*)(sB2 + layer * 64 + c0);
                if (f0) {
                    sT[row0 * ST_S + c0]     += d2[nt * 4 + 0] + bv.x;
                    sT[row0 * ST_S + c0 + 1] += d2[nt * 4 + 1] + bv.y;
                }
                if (f1) {
                    sT[row1 * ST_S + c0]     += d2[nt * 4 + 2] + bv.x;
                    sT[row1 * ST_S + c0 + 1] += d2[nt * 4 + 3] + bv.y;
                }
            }
        }
        __syncwarp();
    }

    // ---- store tile ----
    __syncthreads();
    float* ob = out + (size_t)b * CH * NPIX + n0;
    for (int i = tid; i < TOKB * CH; i += NTHR) {
        int t = i & (TOKB - 1);
        int c = i >> 7;
        ob[(size_t)c * NPIX + t] = sT[t * ST_S + c];
    }
}

// ---------------- launch ----------------
extern "C" void kernel_launch(void* const* d_in, const int* in_sizes, int n_in,
                              void* d_out, int out_size) {
    const float* x    = (const float*)d_in[0];
    const float* prop = (const float*)d_in[1];
    const float* lns  = (const float*)d_in[2];
    const float* lnb  = (const float*)d_in[3];
    const float* w1   = (const float*)d_in[4];
    const float* b1   = (const float*)d_in[5];
    const float* w2   = (const float*)d_in[6];
    const float* b2   = (const float*)d_in[7];
    float* out = (float*)d_out;

    cudaFuncSetAttribute(main_kernel, cudaFuncAttributeMaxDynamicSharedMemorySize, SMEM_BYTES);
    int sel_smem = (NPIX + 260) * 4;
    cudaFuncSetAttribute(select_kernel, cudaFuncAttributeMaxDynamicSharedMemorySize, sel_smem);

    prep_kernel<<<64, 512>>>(w1, w2);
    select_kernel<<<BATCH, 1024, sel_smem>>>(prop);
    dim3 fgrid(NPIX / 1024, BATCH);
    flags1_kernel<<<fgrid, 1024>>>(prop);
    flags2_kernel<<<BATCH, 256>>>();
    dim3 grid(NPIX / TOKB, BATCH);
    main_kernel<<<grid, NTHR, SMEM_BYTES>>>(x, lns, lnb, b1, b2, out);
}

// round 5
// speedup vs baseline: 7.7859x; 1.2947x over previous
#include <cuda_runtime.h>
#include <cuda_fp16.h>
#include <math.h>

#define BATCH 16
#define CH    64
#define NPIX  25600          // 160*160
#define HID   256
#define KSEL  20480          // ceil(25600*0.8)
#define TOKB  128            // tokens per block
#define NTHR  256            // 8 warps

#define ST_S  68             // sT fp32 row stride (272B)
#define W1_S  136            // fp16 elements per row (272B), chunk rows=64
#define W2_S  72             // fp16 elements per row (144B), chunk rows=128

// smem byte offsets (main kernel)
#define OFF_T    0            // 128*68*4  = 34816
#define OFF_W    34816        // two chunk buffers, each 35840 (W1 17408 + W2 18432)
#define BUFB     35840
#define OFF_B1   106496       // 2*256*4 = 2048
#define OFF_B2   108544       // 2*64*4  = 512
#define OFF_LS   109056       // 512
#define OFF_LB   109568       // 512
#define OFF_FLAG 110080       // 128*4   = 512
#define SMEM_BYTES 110592

// ---------------- static scratch ----------------
__device__ unsigned      g_thresh[BATCH];
__device__ int           g_ties[BATCH];
__device__ int           g_eqcnt[BATCH];
__device__ int           g_eqidx[BATCH * NPIX];
__device__ unsigned char g_flags[BATCH * NPIX];
// pre-converted fp16 weights in smem tile layout (chunk = layer*2 + jc)
__device__ unsigned short g_w1[4 * 64 * W1_S];
__device__ unsigned short g_w2[4 * 128 * W2_S];

__device__ __forceinline__ unsigned fkey(float f) {
    unsigned u = __float_as_uint(f);
    return (u & 0x80000000u) ? ~u : (u | 0x80000000u);
}

__device__ __forceinline__ float gelu_f(float v) {
    float inner = 0.7978845608028654f * (v + 0.044715f * v * v * v);
    float t;
    asm("tanh.approx.f32 %0, %1;" : "=f"(t) : "f"(inner));
    return 0.5f * v * (1.0f + t);
}

__device__ __forceinline__ unsigned pack_h2(float2 v) {
    __half2 h = __float22half2_rn(v);
    return *(unsigned*)&h;
}

__device__ __forceinline__ void ldsm_x4t(unsigned r[4], unsigned addr) {
    asm volatile("ldmatrix.sync.aligned.m8n8.x4.trans.shared.b16 {%0,%1,%2,%3}, [%4];"
                 : "=r"(r[0]), "=r"(r[1]), "=r"(r[2]), "=r"(r[3]) : "r"(addr));
}
__device__ __forceinline__ void mma_f16(float* d, const unsigned* a, unsigned b0, unsigned b1) {
    asm volatile("mma.sync.aligned.m16n8k16.row.col.f32.f16.f16.f32 "
                 "{%0,%1,%2,%3}, {%4,%5,%6,%7}, {%8,%9}, {%0,%1,%2,%3};"
                 : "+f"(d[0]), "+f"(d[1]), "+f"(d[2]), "+f"(d[3])
                 : "r"(a[0]), "r"(a[1]), "r"(a[2]), "r"(a[3]), "r"(b0), "r"(b1));
}
__device__ __forceinline__ void cp16(unsigned dst, const void* src) {
    asm volatile("cp.async.cg.shared.global [%0], [%1], 16;" :: "r"(dst), "l"(src));
}

// ---------------- kernel 0: pre-convert weights to fp16 (smem tile layout) --------
__global__ void prep_kernel(const float* __restrict__ w1, const float* __restrict__ w2) {
    int idx = blockIdx.x * blockDim.x + threadIdx.x;
    if (idx >= 2 * CH * HID) return;
    int layer = idx >> 14;
    int rem = idx & 16383;
    {   // w1: [layer][c][j]
        int c = rem >> 8, j = rem & 255;
        __half h = __float2half_rn(w1[idx]);
        int off = (layer * 2 + (j >> 7)) * 64 * W1_S + c * W1_S + (j & 127);
        g_w1[off] = *(unsigned short*)&h;
    }
    {   // w2: [layer][j][c]
        int j = rem >> 6, c = rem & 63;
        __half h = __float2half_rn(w2[idx]);
        int off = (layer * 2 + (j >> 7)) * 128 * W2_S + (j & 127) * W2_S + c;
        g_w2[off] = *(unsigned short*)&h;
    }
}

// ---------------- kernel 1: per-batch radix select (keys cached in smem) ----------
__global__ void select_kernel(const float* __restrict__ prop) {
    int b = blockIdx.x;
    const float* p = prop + (size_t)b * NPIX;
    extern __shared__ unsigned dyn[];
    unsigned* skey = dyn;              // 25600
    unsigned* hist = dyn + NPIX;       // 256
    __shared__ unsigned s_prefix;
    __shared__ int s_k;
    if (threadIdx.x == 0) { s_prefix = 0u; s_k = KSEL; g_eqcnt[b] = 0; }
    for (int i = threadIdx.x; i < NPIX; i += 1024) skey[i] = fkey(p[i]);
    __syncthreads();

    for (int pass = 3; pass >= 0; --pass) {
        int shift = pass * 8;
        if (threadIdx.x < 256) hist[threadIdx.x] = 0u;
        __syncthreads();
        unsigned prefix = s_prefix;
        unsigned highmask = (pass == 3) ? 0u : (0xFFFFFFFFu << (shift + 8));
        for (int i = threadIdx.x; i < NPIX; i += 1024) {
            unsigned u = skey[i];
            if ((u & highmask) == prefix)
                atomicAdd(&hist[(u >> shift) & 255u], 1u);
        }
        __syncthreads();
        if (threadIdx.x == 0) {
            int k = s_k;
            unsigned cum = 0;
            for (int d = 255; d >= 0; --d) {
                unsigned cnt = hist[d];
                if ((unsigned)k <= cum + cnt) {
                    s_prefix = prefix | ((unsigned)d << shift);
                    s_k = k - (int)cum;
                    break;
                }
                cum += cnt;
            }
        }
        __syncthreads();
    }
    if (threadIdx.x == 0) {
        g_thresh[b] = s_prefix;
        g_ties[b]   = s_k;
    }
}

// ---------------- kernel 2a: grid-parallel gt flags + eq capture ----------------
__global__ void flags1_kernel(const float* __restrict__ prop) {
    int b = blockIdx.y;
    int i = blockIdx.x * 1024 + threadIdx.x;
    unsigned T = g_thresh[b];
    unsigned u = fkey(prop[(size_t)b * NPIX + i]);
    unsigned char f = (u > T) ? 1 : 0;
    if (u == T) {
        int s = atomicAdd(&g_eqcnt[b], 1);
        g_eqidx[(size_t)b * NPIX + s] = i;
    }
    g_flags[(size_t)b * NPIX + i] = f;
}

// ---------------- kernel 2b: tie fixup (n expected ~1) ----------------
__global__ void flags2_kernel() {
    int b = blockIdx.x;
    int n = g_eqcnt[b];
    int ties = g_ties[b];
    for (int e = threadIdx.x; e < n; e += 256) {
        int idx = g_eqidx[(size_t)b * NPIX + e];
        int rank = 0;
        for (int q = 0; q < n; ++q)
            rank += (g_eqidx[(size_t)b * NPIX + q] < idx) ? 1 : 0;
        if (rank < ties) g_flags[(size_t)b * NPIX + idx] = 1;
    }
}

// ---------------- kernel 3: fused LN + MLP, single-pass fp16, double-buffered ----
__global__ void __launch_bounds__(NTHR, 2)
main_kernel(const float* __restrict__ x,
            const float* __restrict__ lnscale, const float* __restrict__ lnbias,
            const float* __restrict__ b1g, const float* __restrict__ b2g,
            float* __restrict__ out) {
    extern __shared__ char sm[];
    float* sT  = (float*)(sm + OFF_T);
    float* sB1 = (float*)(sm + OFF_B1);
    float* sB2 = (float*)(sm + OFF_B2);
    float* sLS = (float*)(sm + OFF_LS);
    float* sLB = (float*)(sm + OFF_LB);
    int*   sFlag = (int*)(sm + OFF_FLAG);
    unsigned smem_base = (unsigned)__cvta_generic_to_shared(sm);

    int tid = threadIdx.x;
    int lane = tid & 31, w = tid >> 5;
    int tb = w * 16;
    int b = blockIdx.y, n0 = blockIdx.x * TOKB;

    int r = lane >> 2;           // fragment row within 8
    int c2 = (lane & 3) * 2;     // fragment col pair
    int r15 = lane & 15;
    int colsel = ((lane >> 4) & 1) * 8;
    int row0 = tb + r, row1 = row0 + 8;

    // ---- stage chunk 0 weights (async) ----
    {
        const char* s1 = (const char*)g_w1;
        const char* s2 = (const char*)g_w2;
        unsigned dst = smem_base + OFF_W;
        for (int i = tid * 16; i < 64 * W1_S * 2; i += NTHR * 16) cp16(dst + i, s1 + i);
        for (int i = tid * 16; i < 128 * W2_S * 2; i += NTHR * 16) cp16(dst + 17408 + i, s2 + i);
        asm volatile("cp.async.commit_group;");
    }

    // ---- load x tile: sT[t][c], params, flags ----
    const float* xb = x + (size_t)b * CH * NPIX + n0;
    for (int i = tid; i < TOKB * CH; i += NTHR) {
        int t = i & (TOKB - 1);
        int c = i >> 7;
        sT[t * ST_S + c] = xb[(size_t)c * NPIX + t];
    }
    for (int i = tid; i < 2 * HID; i += NTHR) sB1[i] = b1g[i];
    if (tid < 2 * CH) {
        sB2[tid] = b2g[tid];
        sLS[tid] = lnscale[tid];
        sLB[tid] = lnbias[tid];
    }
    if (tid < TOKB) sFlag[tid] = g_flags[(size_t)b * NPIX + n0 + tid];
    __syncthreads();

    for (int layer = 0; layer < 2; ++layer) {
        // ---- LN stats (warp-local): 2 lanes per token ----
        float mu, rs;
        {
            int t = tb + (lane >> 1), half = lane & 1;
            const float* rowp = sT + t * ST_S + half * 32;
            float s = 0.f, s2 = 0.f;
            #pragma unroll
            for (int k = 0; k < 32; k += 4) {
                float4 v = *(const float4*)(rowp + k);
                s  += v.x + v.y + v.z + v.w;
                s2 += v.x * v.x + v.y * v.y + v.z * v.z + v.w * v.w;
            }
            s  += __shfl_xor_sync(0xffffffffu, s, 1);
            s2 += __shfl_xor_sync(0xffffffffu, s2, 1);
            mu = s * (1.f / 64.f);
            float var = s2 * (1.f / 64.f) - mu * mu;
            rs = rsqrtf(var + 1e-5f);
        }
        float mu0 = __shfl_sync(0xffffffffu, mu, r << 1);
        float rs0 = __shfl_sync(0xffffffffu, rs, r << 1);
        float mu1 = __shfl_sync(0xffffffffu, mu, (r << 1) + 16);
        float rs1 = __shfl_sync(0xffffffffu, rs, (r << 1) + 16);

        // ---- build GEMM1 A-fragments (Xn) in registers, fp16 ----
        unsigned aX[16];
        #pragma unroll
        for (int kt = 0; kt < 4; ++kt) {
            int cA = kt * 16 + c2;
            float2 lsA = *(const float2*)(sLS + layer * 64 + cA);
            float2 lbA = *(const float2*)(sLB + layer * 64 + cA);
            float2 lsB = *(const float2*)(sLS + layer * 64 + cA + 8);
            float2 lbB = *(const float2*)(sLB + layer * 64 + cA + 8);
            float2 v;
            v = *(const float2*)(sT + row0 * ST_S + cA);
            v.x = (v.x - mu0) * rs0 * lsA.x + lbA.x;
            v.y = (v.y - mu0) * rs0 * lsA.y + lbA.y;
            aX[kt * 4 + 0] = pack_h2(v);
            v = *(const float2*)(sT + row1 * ST_S + cA);
            v.x = (v.x - mu1) * rs1 * lsA.x + lbA.x;
            v.y = (v.y - mu1) * rs1 * lsA.y + lbA.y;
            aX[kt * 4 + 1] = pack_h2(v);
            v = *(const float2*)(sT + row0 * ST_S + cA + 8);
            v.x = (v.x - mu0) * rs0 * lsB.x + lbB.x;
            v.y = (v.y - mu0) * rs0 * lsB.y + lbB.y;
            aX[kt * 4 + 2] = pack_h2(v);
            v = *(const float2*)(sT + row1 * ST_S + cA + 8);
            v.x = (v.x - mu1) * rs1 * lsB.x + lbB.x;
            v.y = (v.y - mu1) * rs1 * lsB.y + lbB.y;
            aX[kt * 4 + 3] = pack_h2(v);
        }

        float d2[32];
        #pragma unroll
        for (int i = 0; i < 32; ++i) d2[i] = 0.f;

        for (int jc = 0; jc < 2; ++jc) {
            int ch = layer * 2 + jc;
            int buf = ch & 1;
            unsigned wbase = smem_base + OFF_W + buf * BUFB;

            // ---- prefetch next chunk into other buffer ----
            if (ch + 1 < 4) {
                int nc = ch + 1;
                const char* s1 = (const char*)(g_w1 + nc * 64 * W1_S);
                const char* s2 = (const char*)(g_w2 + nc * 128 * W2_S);
                unsigned dst = smem_base + OFF_W + (buf ^ 1) * BUFB;
                for (int i = tid * 16; i < 64 * W1_S * 2; i += NTHR * 16) cp16(dst + i, s1 + i);
                for (int i = tid * 16; i < 128 * W2_S * 2; i += NTHR * 16) cp16(dst + 17408 + i, s2 + i);
                asm volatile("cp.async.commit_group;");
                asm volatile("cp.async.wait_group 1;");
            } else {
                asm volatile("cp.async.wait_group 0;");
            }
            __syncthreads();   // current chunk weights visible to all warps

            for (int jg = 0; jg < 8; ++jg) {
                // ---- GEMM1: d1[16 tok x 16 j], K=64, single-pass fp16 ----
                float d1[8];
                #pragma unroll
                for (int i = 0; i < 8; ++i) d1[i] = 0.f;
                #pragma unroll
                for (int kt = 0; kt < 4; ++kt) {
                    unsigned bh[4];
                    unsigned boff = (unsigned)((kt * 16 + r15) * W1_S + jg * 16 + colsel) * 2;
                    ldsm_x4t(bh, wbase + boff);
                    mma_f16(d1,     aX + kt * 4, bh[0], bh[1]);
                    mma_f16(d1 + 4, aX + kt * 4, bh[2], bh[3]);
                }
                // ---- epilogue in regs: bias + gelu -> GEMM2 A frags ----
                unsigned a2[4];
                {
                    int j0 = jc * 128 + jg * 16;
                    const float* bptr = sB1 + layer * HID + j0;
                    float2 b0 = *(const float2*)(bptr + c2);
                    float2 b8 = *(const float2*)(bptr + 8 + c2);
                    float2 v;
                    v.x = gelu_f(d1[0] + b0.x); v.y = gelu_f(d1[1] + b0.y); a2[0] = pack_h2(v);
                    v.x = gelu_f(d1[2] + b0.x); v.y = gelu_f(d1[3] + b0.y); a2[1] = pack_h2(v);
                    v.x = gelu_f(d1[4] + b8.x); v.y = gelu_f(d1[5] + b8.y); a2[2] = pack_h2(v);
                    v.x = gelu_f(d1[6] + b8.x); v.y = gelu_f(d1[7] + b8.y); a2[3] = pack_h2(v);
                }
                // ---- GEMM2 partial: k-tile = this jg, N=64, single-pass fp16 ----
                #pragma unroll
                for (int np = 0; np < 4; ++np) {
                    unsigned bh[4];
                    unsigned boff = (unsigned)((jg * 16 + r15) * W2_S + np * 16 + colsel) * 2;
                    ldsm_x4t(bh, wbase + 17408 + boff);
                    mma_f16(d2 + np * 8,     a2, bh[0], bh[1]);
                    mma_f16(d2 + np * 8 + 4, a2, bh[2], bh[3]);
                }
            }
            __syncthreads();   // all warps done with this buffer before next overwrite
        }

        // ---- gated residual add into sT (warp-local rows) ----
        {
            int f0 = sFlag[row0], f1 = sFlag[row1];
            #pragma unroll
            for (int nt = 0; nt < 8; ++nt) {
                int c0 = nt * 8 + c2;
                float2 bv = *(const float2*)(sB2 + layer * 64 + c0);
                if (f0) {
                    sT[row0 * ST_S + c0]     += d2[nt * 4 + 0] + bv.x;
                    sT[row0 * ST_S + c0 + 1] += d2[nt * 4 + 1] + bv.y;
                }
                if (f1) {
                    sT[row1 * ST_S + c0]     += d2[nt * 4 + 2] + bv.x;
                    sT[row1 * ST_S + c0 + 1] += d2[nt * 4 + 3] + bv.y;
                }
            }
        }
        __syncwarp();
    }

    // ---- store tile ----
    __syncthreads();
    float* ob = out + (size_t)b * CH * NPIX + n0;
    for (int i = tid; i < TOKB * CH; i += NTHR) {
        int t = i & (TOKB - 1);
        int c = i >> 7;
        ob[(size_t)c * NPIX + t] = sT[t * ST_S + c];
    }
}

// ---------------- launch ----------------
extern "C" void kernel_launch(void* const* d_in, const int* in_sizes, int n_in,
                              void* d_out, int out_size) {
    const float* x    = (const float*)d_in[0];
    const float* prop = (const float*)d_in[1];
    const float* lns  = (const float*)d_in[2];
    const float* lnb  = (const float*)d_in[3];
    const float* w1   = (const float*)d_in[4];
    const float* b1   = (const float*)d_in[5];
    const float* w2   = (const float*)d_in[6];
    const float* b2   = (const float*)d_in[7];
    float* out = (float*)d_out;

    cudaFuncSetAttribute(main_kernel, cudaFuncAttributeMaxDynamicSharedMemorySize, SMEM_BYTES);
    int sel_smem = (NPIX + 260) * 4;
    cudaFuncSetAttribute(select_kernel, cudaFuncAttributeMaxDynamicSharedMemorySize, sel_smem);

    prep_kernel<<<64, 512>>>(w1, w2);
    select_kernel<<<BATCH, 1024, sel_smem>>>(prop);
    dim3 fgrid(NPIX / 1024, BATCH);
    flags1_kernel<<<fgrid, 1024>>>(prop);
    flags2_kernel<<<BATCH, 256>>>();
    dim3 grid(NPIX / TOKB, BATCH);
    main_kernel<<<grid, NTHR, SMEM_BYTES>>>(x, lns, lnb, b1, b2, out);
}

// round 7
// speedup vs baseline: 8.3555x; 1.0731x over previous
#include <cuda_runtime.h>
#include <cuda_fp16.h>
#include <math.h>

#define BATCH 16
#define CH    64
#define NPIX  25600          // 160*160
#define HID   256
#define KSEL  20480          // ceil(25600*0.8)
#define TOKB  128            // tokens per block
#define NTHR  256            // 8 warps

#define ST_S  68             // sT fp32 row stride (272B)
#define W1_S  136            // fp16 elements per row (272B), chunk rows=64
#define W2_S  72             // fp16 elements per row (144B), chunk rows=128

// smem byte offsets (main kernel)
#define OFF_T    0            // 128*68*4  = 34816
#define OFF_W    34816        // two chunk buffers, each 35840 (W1 17408 + W2 18432)
#define BUFB     35840
#define OFF_B1   106496       // 256 u32 (h2-packed bias1)
#define OFF_B2   108544       // 2*64*4  = 512
#define OFF_LS   109056       // 512
#define OFF_LB   109568       // 512
#define OFF_FLAG 110080       // 128*4   = 512
#define SMEM_BYTES 110592

// ---------------- static scratch ----------------
__device__ unsigned      g_thresh[BATCH];
__device__ int           g_ties[BATCH];
__device__ unsigned char g_flags[BATCH * NPIX];
// pre-converted fp16 weights in smem tile layout (chunk = layer*2 + jc)
__device__ unsigned short g_w1[4 * 64 * W1_S];
__device__ unsigned short g_w2[4 * 128 * W2_S];

__device__ __forceinline__ unsigned fkey(float f) {
    unsigned u = __float_as_uint(f);
    return (u & 0x80000000u) ? ~u : (u | 0x80000000u);
}

__device__ __forceinline__ unsigned pack_h2(float2 v) {
    __half2 h = __float22half2_rn(v);
    return *(unsigned*)&h;
}

// gelu on a packed half2 (tanh approximation, all-fp16 math)
__device__ __forceinline__ unsigned gelu_h2(unsigned vu) {
    __half2 v = *(__half2*)&vu;
    const __half2 k0  = __floats2half2_rn(0.7978845608f, 0.7978845608f);
    const __half2 k01 = __floats2half2_rn(0.0356774081f, 0.0356774081f);  // k0*0.044715
    const __half2 hf  = __floats2half2_rn(0.5f, 0.5f);
    __half2 u = __hmul2(v, v);
    __half2 w = __hmul2(u, v);
    __half2 inner = __hfma2(w, k01, __hmul2(v, k0));
    unsigned tin = *(unsigned*)&inner, tout;
    asm("tanh.approx.f16x2 %0, %1;" : "=r"(tout) : "r"(tin));
    __half2 t = *(__half2*)&tout;
    __half2 hv = __hmul2(v, hf);
    __half2 res = __hfma2(hv, t, hv);
    return *(unsigned*)&res;
}

__device__ __forceinline__ void ldsm_x4t(unsigned r[4], unsigned addr) {
    asm volatile("ldmatrix.sync.aligned.m8n8.x4.trans.shared.b16 {%0,%1,%2,%3}, [%4];"
                 : "=r"(r[0]), "=r"(r[1]), "=r"(r[2]), "=r"(r[3]) : "r"(addr));
}
__device__ __forceinline__ void mma_f16(float* d, const unsigned* a, unsigned b0, unsigned b1) {
    asm volatile("mma.sync.aligned.m16n8k16.row.col.f32.f16.f16.f32 "
                 "{%0,%1,%2,%3}, {%4,%5,%6,%7}, {%8,%9}, {%0,%1,%2,%3};"
                 : "+f"(d[0]), "+f"(d[1]), "+f"(d[2]), "+f"(d[3])
                 : "r"(a[0]), "r"(a[1]), "r"(a[2]), "r"(a[3]), "r"(b0), "r"(b1));
}
__device__ __forceinline__ void cp16(unsigned dst, const void* src) {
    asm volatile("cp.async.cg.shared.global [%0], [%1], 16;" :: "r"(dst), "l"(src));
}

// ---------------- kernel 0: pre-convert weights to fp16 (smem tile layout) --------
__global__ void prep_kernel(const float* __restrict__ w1, const float* __restrict__ w2) {
    int idx = blockIdx.x * blockDim.x + threadIdx.x;
    if (idx >= 2 * CH * HID) return;
    int layer = idx >> 14;
    int rem = idx & 16383;
    {   // w1: [layer][c][j]
        int c = rem >> 8, j = rem & 255;
        __half h = __float2half_rn(w1[idx]);
        int off = (layer * 2 + (j >> 7)) * 64 * W1_S + c * W1_S + (j & 127);
        g_w1[off] = *(unsigned short*)&h;
    }
    {   // w2: [layer][j][c]
        int j = rem >> 6, c = rem & 63;
        __half h = __float2half_rn(w2[idx]);
        int off = (layer * 2 + (j >> 7)) * 128 * W2_S + (j & 127) * W2_S + c;
        g_w2[off] = *(unsigned short*)&h;
    }
}

// ---------------- kernel 1: fused per-batch radix select + flags ----------------
__global__ void select_flags_kernel(const float* __restrict__ prop) {
    int b = blockIdx.x;
    const float* p = prop + (size_t)b * NPIX;
    extern __shared__ unsigned dyn[];
    unsigned* skey = dyn;              // 25600 keys
    unsigned* hist = dyn + NPIX;       // 256
    __shared__ unsigned s_prefix;
    __shared__ int s_k;
    __shared__ int s_carry;
    __shared__ int warp_sums[32];
    int tid = threadIdx.x;
    if (tid == 0) { s_prefix = 0u; s_k = KSEL; s_carry = 0; }
    for (int i = tid; i < NPIX; i += 1024) skey[i] = fkey(p[i]);
    __syncthreads();

    for (int pass = 3; pass >= 0; --pass) {
        int shift = pass * 8;
        if (tid < 256) hist[tid] = 0u;
        __syncthreads();
        unsigned prefix = s_prefix;
        unsigned highmask = (pass == 3) ? 0u : (0xFFFFFFFFu << (shift + 8));
        for (int i = tid; i < NPIX; i += 1024) {
            unsigned u = skey[i];
            if ((u & highmask) == prefix)
                atomicAdd(&hist[(u >> shift) & 255u], 1u);
        }
        __syncthreads();
        if (tid == 0) {
            int k = s_k;
            unsigned cum = 0;
            for (int d = 255; d >= 0; --d) {
                unsigned cnt = hist[d];
                if ((unsigned)k <= cum + cnt) {
                    s_prefix = prefix | ((unsigned)d << shift);
                    s_k = k - (int)cum;
                    break;
                }
                cum += cnt;
            }
        }
        __syncthreads();
    }
    unsigned T = s_prefix;
    int ties = s_k;
    int lane = tid & 31, w = tid >> 5;
    for (int base = 0; base < NPIX; base += 1024) {
        int i = base + tid;
        unsigned u = skey[i];
        int gt = (u > T), eq = (u == T);
        unsigned ball = __ballot_sync(0xffffffffu, eq);
        int pre = __popc(ball & ((1u << lane) - 1u));
        if (lane == 0) warp_sums[w] = __popc(ball);
        __syncthreads();
        int woff = 0;
        for (int xw = 0; xw < w; ++xw) woff += warp_sums[xw];
        int rank = s_carry + woff + pre;
        g_flags[(size_t)b * NPIX + i] = (unsigned char)(gt || (eq && rank < ties));
        __syncthreads();
        if (tid == 0) {
            int tot = 0;
            for (int xw = 0; xw < 32; ++xw) tot += warp_sums[xw];
            s_carry += tot;
        }
        __syncthreads();
    }
}

// ---------------- kernel 2: fused LN + MLP, fp16 single-pass, h2 gelu ----------
__global__ void __launch_bounds__(NTHR, 2)
main_kernel(const float* __restrict__ x,
            const float* __restrict__ lnscale, const float* __restrict__ lnbias,
            const float* __restrict__ b1g, const float* __restrict__ b2g,
            float* __restrict__ out) {
    extern __shared__ char sm[];
    float* sT  = (float*)(sm + OFF_T);
    unsigned* sB1h = (unsigned*)(sm + OFF_B1);
    float* sB2 = (float*)(sm + OFF_B2);
    float* sLS = (float*)(sm + OFF_LS);
    float* sLB = (float*)(sm + OFF_LB);
    int*   sFlag = (int*)(sm + OFF_FLAG);
    unsigned smem_base = (unsigned)__cvta_generic_to_shared(sm);

    int tid = threadIdx.x;
    int lane = tid & 31, w = tid >> 5;
    int tb = w * 16;
    int b = blockIdx.y, n0 = blockIdx.x * TOKB;

    int r = lane >> 2;           // fragment row within 8
    int c2 = (lane & 3) * 2;     // fragment col pair
    int r15 = lane & 15;
    int colsel = ((lane >> 4) & 1) * 8;
    int row0 = tb + r, row1 = row0 + 8;

    // ---- stage chunk 0 weights (async) ----
    {
        const char* s1 = (const char*)g_w1;
        const char* s2 = (const char*)g_w2;
        unsigned dst = smem_base + OFF_W;
        for (int i = tid * 16; i < 64 * W1_S * 2; i += NTHR * 16) cp16(dst + i, s1 + i);
        for (int i = tid * 16; i < 128 * W2_S * 2; i += NTHR * 16) cp16(dst + 17408 + i, s2 + i);
        asm volatile("cp.async.commit_group;");
    }

    // ---- load x tile: sT[t][c], params, flags ----
    const float* xb = x + (size_t)b * CH * NPIX + n0;
    for (int i = tid; i < TOKB * CH; i += NTHR) {
        int t = i & (TOKB - 1);
        int c = i >> 7;
        sT[t * ST_S + c] = xb[(size_t)c * NPIX + t];
    }
    if (tid < HID) sB1h[tid] = pack_h2(make_float2(b1g[2 * tid], b1g[2 * tid + 1]));
    if (tid < 2 * CH) {
        sB2[tid] = b2g[tid];
        sLS[tid] = lnscale[tid];
        sLB[tid] = lnbias[tid];
    }
    if (tid < TOKB) sFlag[tid] = g_flags[(size_t)b * NPIX + n0 + tid];
    __syncthreads();

    for (int layer = 0; layer < 2; ++layer) {
        // ---- LN stats (warp-local): 2 lanes per token ----
        float mu, rs;
        {
            int t = tb + (lane >> 1), half = lane & 1;
            const float* rowp = sT + t * ST_S + half * 32;
            float s = 0.f, s2 = 0.f;
            #pragma unroll
            for (int k = 0; k < 32; k += 4) {
                float4 v = *(const float4*)(rowp + k);
                s  += v.x + v.y + v.z + v.w;
                s2 += v.x * v.x + v.y * v.y + v.z * v.z + v.w * v.w;
            }
            s  += __shfl_xor_sync(0xffffffffu, s, 1);
            s2 += __shfl_xor_sync(0xffffffffu, s2, 1);
            mu = s * (1.f / 64.f);
            float var = s2 * (1.f / 64.f) - mu * mu;
            rs = rsqrtf(var + 1e-5f);
        }
        float mu0 = __shfl_sync(0xffffffffu, mu, r << 1);
        float rs0 = __shfl_sync(0xffffffffu, rs, r << 1);
        float mu1 = __shfl_sync(0xffffffffu, mu, (r << 1) + 16);
        float rs1 = __shfl_sync(0xffffffffu, rs, (r << 1) + 16);

        // ---- build GEMM1 A-fragments (Xn) in registers, fp16 ----
        unsigned aX[16];
        #pragma unroll
        for (int kt = 0; kt < 4; ++kt) {
            int cA = kt * 16 + c2;
            float2 lsA = *(const float2*)(sLS + layer * 64 + cA);
            float2 lbA = *(const float2*)(sLB + layer * 64 + cA);
            float2 lsB = *(const float2*)(sLS + layer * 64 + cA + 8);
            float2 lbB = *(const float2*)(sLB + layer * 64 + cA + 8);
            float2 v;
            v = *(const float2*)(sT + row0 * ST_S + cA);
            v.x = (v.x - mu0) * rs0 * lsA.x + lbA.x;
            v.y = (v.y - mu0) * rs0 * lsA.y + lbA.y;
            aX[kt * 4 + 0] = pack_h2(v);
            v = *(const float2*)(sT + row1 * ST_S + cA);
            v.x = (v.x - mu1) * rs1 * lsA.x + lbA.x;
            v.y = (v.y - mu1) * rs1 * lsA.y + lbA.y;
            aX[kt * 4 + 1] = pack_h2(v);
            v = *(const float2*)(sT + row0 * ST_S + cA + 8);
            v.x = (v.x - mu0) * rs0 * lsB.x + lbB.x;
            v.y = (v.y - mu0) * rs0 * lsB.y + lbB.y;
            aX[kt * 4 + 2] = pack_h2(v);
            v = *(const float2*)(sT + row1 * ST_S + cA + 8);
            v.x = (v.x - mu1) * rs1 * lsB.x + lbB.x;
            v.y = (v.y - mu1) * rs1 * lsB.y + lbB.y;
            aX[kt * 4 + 3] = pack_h2(v);
        }

        float d2[32];
        #pragma unroll
        for (int i = 0; i < 32; ++i) d2[i] = 0.f;

        for (int jc = 0; jc < 2; ++jc) {
            int ch = layer * 2 + jc;
            int buf = ch & 1;
            unsigned wbase = smem_base + OFF_W + buf * BUFB;

            // ---- prefetch next chunk into other buffer ----
            if (ch + 1 < 4) {
                int nc = ch + 1;
                const char* s1 = (const char*)(g_w1 + nc * 64 * W1_S);
                const char* s2 = (const char*)(g_w2 + nc * 128 * W2_S);
                unsigned dst = smem_base + OFF_W + (buf ^ 1) * BUFB;
                for (int i = tid * 16; i < 64 * W1_S * 2; i += NTHR * 16) cp16(dst + i, s1 + i);
                for (int i = tid * 16; i < 128 * W2_S * 2; i += NTHR * 16) cp16(dst + 17408 + i, s2 + i);
                asm volatile("cp.async.commit_group;");
                asm volatile("cp.async.wait_group 1;");
            } else {
                asm volatile("cp.async.wait_group 0;");
            }
            __syncthreads();   // current chunk weights visible to all warps

            for (int jg = 0; jg < 8; ++jg) {
                // ---- GEMM1: d1[16 tok x 16 j], K=64, single-pass fp16 ----
                float d1[8];
                #pragma unroll
                for (int i = 0; i < 8; ++i) d1[i] = 0.f;
                #pragma unroll
                for (int kt = 0; kt < 4; ++kt) {
                    unsigned bh[4];
                    unsigned boff = (unsigned)((kt * 16 + r15) * W1_S + jg * 16 + colsel) * 2;
                    ldsm_x4t(bh, wbase + boff);
                    mma_f16(d1,     aX + kt * 4, bh[0], bh[1]);
                    mma_f16(d1 + 4, aX + kt * 4, bh[2], bh[3]);
                }
                // ---- epilogue in h2: pack + bias + gelu -> GEMM2 A frags ----
                unsigned a2[4];
                {
                    int j0 = jc * 128 + jg * 16;
                    int pb = (layer * HID + j0) >> 1;
                    unsigned b0 = sB1h[pb + (c2 >> 1)];
                    unsigned b8 = sB1h[pb + 4 + (c2 >> 1)];
                    __half2 b0h = *(__half2*)&b0, b8h = *(__half2*)&b8;
                    __half2 t;
                    t = __hadd2(*(__half2*)&(unsigned&)(a2[0] = pack_h2(make_float2(d1[0], d1[1]))), b0h);
                    a2[0] = gelu_h2(*(unsigned*)&t);
                    t = __hadd2(*(__half2*)&(unsigned&)(a2[1] = pack_h2(make_float2(d1[2], d1[3]))), b0h);
                    a2[1] = gelu_h2(*(unsigned*)&t);
                    t = __hadd2(*(__half2*)&(unsigned&)(a2[2] = pack_h2(make_float2(d1[4], d1[5]))), b8h);
                    a2[2] = gelu_h2(*(unsigned*)&t);
                    t = __hadd2(*(__half2*)&(unsigned&)(a2[3] = pack_h2(make_float2(d1[6], d1[7]))), b8h);
                    a2[3] = gelu_h2(*(unsigned*)&t);
                }
                // ---- GEMM2 partial: k-tile = this jg, N=64, fp16 ----
                #pragma unroll
                for (int np = 0; np < 4; ++np) {
                    unsigned bh[4];
                    unsigned boff = (unsigned)((jg * 16 + r15) * W2_S + np * 16 + colsel) * 2;
                    ldsm_x4t(bh, wbase + 17408 + boff);
                    mma_f16(d2 + np * 8,     a2, bh[0], bh[1]);
                    mma_f16(d2 + np * 8 + 4, a2, bh[2], bh[3]);
                }
            }
            __syncthreads();   // all warps done with this buffer before next overwrite
        }

        // ---- gated residual add into sT (warp-local rows) ----
        {
            int f0 = sFlag[row0], f1 = sFlag[row1];
            #pragma unroll
            for (int nt = 0; nt < 8; ++nt) {
                int c0 = nt * 8 + c2;
                float2 bv = *(const float2*)(sB2 + layer * 64 + c0);
                if (f0) {
                    sT[row0 * ST_S + c0]     += d2[nt * 4 + 0] + bv.x;
                    sT[row0 * ST_S + c0 + 1] += d2[nt * 4 + 1] + bv.y;
                }
                if (f1) {
                    sT[row1 * ST_S + c0]     += d2[nt * 4 + 2] + bv.x;
                    sT[row1 * ST_S + c0 + 1] += d2[nt * 4 + 3] + bv.y;
                }
            }
        }
        __syncwarp();
    }

    // ---- store tile ----
    __syncthreads();
    float* ob = out + (size_t)b * CH * NPIX + n0;
    for (int i = tid; i < TOKB * CH; i += NTHR) {
        int t = i & (TOKB - 1);
        int c = i >> 7;
        ob[(size_t)c * NPIX + t] = sT[t * ST_S + c];
    }
}

// ---------------- launch ----------------
extern "C" void kernel_launch(void* const* d_in, const int* in_sizes, int n_in,
                              void* d_out, int out_size) {
    const float* x    = (const float*)d_in[0];
    const float* prop = (const float*)d_in[1];
    const float* lns  = (const float*)d_in[2];
    const float* lnb  = (const float*)d_in[3];
    const float* w1   = (const float*)d_in[4];
    const float* b1   = (const float*)d_in[5];
    const float* w2   = (const float*)d_in[6];
    const float* b2   = (const float*)d_in[7];
    float* out = (float*)d_out;

    cudaFuncSetAttribute(main_kernel, cudaFuncAttributeMaxDynamicSharedMemorySize, SMEM_BYTES);
    int sel_smem = (NPIX + 260) * 4;
    cudaFuncSetAttribute(select_flags_kernel, cudaFuncAttributeMaxDynamicSharedMemorySize, sel_smem);

    prep_kernel<<<64, 512>>>(w1, w2);
    select_flags_kernel<<<BATCH, 1024, sel_smem>>>(prop);
    dim3 grid(NPIX / TOKB, BATCH);
    main_kernel<<<grid, NTHR, SMEM_BYTES>>>(x, lns, lnb, b1, b2, out);
}